// round 5
// baseline (speedup 1.0000x reference)
#include <cuda_runtime.h>

#define NMAX 8192
#define D    128
#define RB   64      // rows per block
#define CB   128     // cols per tile
#define WY   130     // padded row width of Ys (conflict-free stride)

__device__ float g_sq[NMAX];
__device__ int   g_lbl[NMAX];
__device__ float g_ap[NMAX];
__device__ float g_an[NMAX];
__device__ int   g_is64;      // 1 if targets buffer is int64-laid-out

// ---------------------------------------------------------------------------
// Detect int32 vs int64 label layout (deterministic, input-dependent only).
// View buffer as int32[n]. If ALL odd words are zero -> int64 layout
// (labels in even words). Random labels in [0,512) make false positives
// impossible in practice. Single block.
// ---------------------------------------------------------------------------
__global__ void detect_kernel(const int* __restrict__ T32, int n) {
    __shared__ int any_odd;
    if (threadIdx.x == 0) any_odd = 0;
    __syncthreads();
    int local = 0;
    for (int i = 1 + 2 * threadIdx.x; i < n; i += 2 * blockDim.x)
        local |= T32[i];
    if (local) atomicOr(&any_odd, 1);
    __syncthreads();
    if (threadIdx.x == 0) g_is64 = (any_odd == 0) ? 1 : 0;
}

// ---------------------------------------------------------------------------
// Prep: squared norms + labels. One warp per row (d=128 -> float4/lane).
// ---------------------------------------------------------------------------
__global__ void prep_kernel(const float* __restrict__ X,
                            const int* __restrict__ T32, int n) {
    int warp = (blockIdx.x * blockDim.x + threadIdx.x) >> 5;
    int lane = threadIdx.x & 31;
    if (warp >= n) return;
    float4 v = reinterpret_cast<const float4*>(X)[(size_t)warp * 32 + lane];
    float s = v.x * v.x + v.y * v.y + v.z * v.z + v.w * v.w;
#pragma unroll
    for (int o = 16; o; o >>= 1) s += __shfl_xor_sync(0xffffffffu, s, o);
    if (lane == 0) {
        g_sq[warp]  = s;
        // int64 layout: label i = low word at index 2i (labels < 2^31).
        g_lbl[warp] = g_is64 ? T32[2 * warp] : T32[warp];
    }
}

// ---------------------------------------------------------------------------
// Main: fused Gram tile + batch-hard mining on squared distances.
// 128 threads = 16 tx (8 cols each, stride 16) x 8 ty (8 rows each).
// Accumulators packed 2 rows per 64-bit register via fma.rn.f32x2
// (validated equivalent to scalar FMA in R2/R3).
// ---------------------------------------------------------------------------
__global__ void __launch_bounds__(128, 1)
triplet_main(const float* __restrict__ X, int n) {
    extern __shared__ float smem[];
    float* XsT = smem;                 // [D][64]  k-major row tile
    float* Ys  = smem + D * 64;        // [CB][WY] c-major col tile
    float* sqS = Ys + CB * WY;         // [CB]
    int*   lbS = (int*)(sqS + CB);     // [CB]

    const int tid   = threadIdx.x;
    const int tx    = tid & 15;
    const int ty    = tid >> 4;        // 0..7
    const int rbase = blockIdx.x * RB;
    const int r0    = ty * 8;          // this thread's 8 rows: r0..r0+7

    // Fill XsT (transpose). Lanes vary over r -> conflict-free STS.
    for (int e = tid; e < RB * 32; e += 128) {
        int r = e & 63, kq = e >> 6;
        float4 v = reinterpret_cast<const float4*>(X)[(size_t)(rbase + r) * 32 + kq];
        XsT[(4 * kq + 0) * 64 + r] = v.x;
        XsT[(4 * kq + 1) * 64 + r] = v.y;
        XsT[(4 * kq + 2) * 64 + r] = v.z;
        XsT[(4 * kq + 3) * 64 + r] = v.w;
    }

    float sqA[8]; int lbA[8];
#pragma unroll
    for (int i = 0; i < 8; i++) {
        sqA[i] = g_sq[rbase + r0 + i];
        lbA[i] = g_lbl[rbase + r0 + i];
    }

    float ap2[8], an2[8];
#pragma unroll
    for (int i = 0; i < 8; i++) { ap2[i] = -1e30f; an2[i] = 3e38f; }

    for (int cb = 0; cb < n; cb += CB) {
        __syncthreads();  // covers XsT fill (first iter) and prior-tile smem reads
        // Fill Ys: coalesced float2 global reads, conflict-free STS (W=130).
        for (int e = tid; e < CB * 64; e += 128) {
            int c = e >> 6, kq = e & 63;
            float2 v = reinterpret_cast<const float2*>(X)[(size_t)(cb + c) * 64 + kq];
            *reinterpret_cast<float2*>(&Ys[c * WY + 2 * kq]) = v;
        }
        if (tid < CB) { sqS[tid] = g_sq[cb + tid]; lbS[tid] = g_lbl[cb + tid]; }
        __syncthreads();

        unsigned long long acc[4][8];  // [rowpair p][col j]
#pragma unroll
        for (int p = 0; p < 4; p++)
#pragma unroll
            for (int j = 0; j < 8; j++) acc[p][j] = 0ull;

#pragma unroll 4
        for (int k = 0; k < D; k++) {
            unsigned long long xa[4];
#pragma unroll
            for (int p = 0; p < 4; p++)
                xa[p] = *reinterpret_cast<const unsigned long long*>(
                            &XsT[k * 64 + r0 + 2 * p]);
#pragma unroll
            for (int j = 0; j < 8; j++) {
                float b = Ys[(tx + 16 * j) * WY + k];
                unsigned long long bb;
                asm("mov.b64 %0, {%1, %1};" : "=l"(bb) : "r"(__float_as_uint(b)));
#pragma unroll
                for (int p = 0; p < 4; p++)
                    asm("fma.rn.f32x2 %0, %1, %2, %0;"
                        : "+l"(acc[p][j]) : "l"(xa[p]), "l"(bb));
            }
        }

        // Mining epilogue on squared distances (sqrt deferred: monotone).
#pragma unroll
        for (int j = 0; j < 8; j++) {
            int   c  = tx + 16 * j;
            float sb = sqS[c];
            int   lb = lbS[c];
#pragma unroll
            for (int p = 0; p < 4; p++) {
                float lo = __uint_as_float((unsigned)(acc[p][j] & 0xffffffffu));
                float hi = __uint_as_float((unsigned)(acc[p][j] >> 32));
                float d2a = sqA[2 * p]     + sb - 2.0f * lo;
                float d2b = sqA[2 * p + 1] + sb - 2.0f * hi;
                if (lbA[2 * p] == lb) ap2[2 * p] = fmaxf(ap2[2 * p], d2a);
                else                  an2[2 * p] = fminf(an2[2 * p], d2a);
                if (lbA[2 * p + 1] == lb) ap2[2 * p + 1] = fmaxf(ap2[2 * p + 1], d2b);
                else                      an2[2 * p + 1] = fminf(an2[2 * p + 1], d2b);
            }
        }
    }

    // Reduce across the 16 tx lanes sharing each row (xor<=8 stays in half-warp).
#pragma unroll
    for (int i = 0; i < 8; i++) {
        float a = ap2[i], b = an2[i];
#pragma unroll
        for (int o = 8; o; o >>= 1) {
            a = fmaxf(a, __shfl_xor_sync(0xffffffffu, a, o));
            b = fminf(b, __shfl_xor_sync(0xffffffffu, b, o));
        }
        if (tx == 0) {
            int row = rbase + r0 + i;
            g_ap[row] = sqrtf(fmaxf(a, 1e-12f));
            g_an[row] = sqrtf(fmaxf(b, 1e-12f));
        }
    }
}

// ---------------------------------------------------------------------------
// Final: loss = mean(max(0, margin - (an - ap))), prec = mean(an > ap).
// ---------------------------------------------------------------------------
__global__ void triplet_final(float* __restrict__ out, int n, int out_size) {
    __shared__ float sL[256], sP[256];
    int tid = threadIdx.x;
    float ls = 0.f, ps = 0.f;
    for (int i = tid; i < n; i += 256) {
        float ap = g_ap[i], an = g_an[i];
        ls += fmaxf(0.0f, 0.3f - (an - ap));
        ps += (an > ap) ? 1.0f : 0.0f;
    }
    sL[tid] = ls; sP[tid] = ps;
    __syncthreads();
    for (int s = 128; s; s >>= 1) {
        if (tid < s) { sL[tid] += sL[tid + s]; sP[tid] += sP[tid + s]; }
        __syncthreads();
    }
    if (tid == 0) {
        out[0] = sL[0] / (float)n;
        if (out_size > 1) out[1] = sP[0] / (float)n;
    }
    for (int i = 2 + tid; i < out_size; i += 256) out[i] = 0.0f;
}

// ---------------------------------------------------------------------------
extern "C" void kernel_launch(void* const* d_in, const int* in_sizes, int n_in,
                              void* d_out, int out_size) {
    const float* X   = (const float*)d_in[0];
    const int*   T32 = (const int*)d_in[1];
    int n = in_sizes[1];                 // 8192 labels (d fixed at 128)

    detect_kernel<<<1, 256>>>(T32, n);
    prep_kernel<<<(n + 7) / 8, 256>>>(X, T32, n);

    size_t smem_bytes = (size_t)(D * 64 + CB * WY + CB) * sizeof(float)
                      + (size_t)CB * sizeof(int);
    cudaFuncSetAttribute(triplet_main,
                         cudaFuncAttributeMaxDynamicSharedMemorySize,
                         (int)smem_bytes);
    triplet_main<<<n / RB, 128, smem_bytes>>>(X, n);

    triplet_final<<<1, 256>>>((float*)d_out, n, out_size);
}

// round 7
// speedup vs baseline: 2.4259x; 2.4259x over previous
#include <cuda_runtime.h>
#include <cuda_bf16.h>
#include <mma.h>
#include <cstdint>

using namespace nvcuda;

#define NMAX 8192
#define DD   128
#define LDA  136   // bf16 elems per smem row (pad kills LDSM conflicts)
#define LDC  132   // f32 elems per C row

__device__ float        g_sq[NMAX];
__device__ int          g_lbl[NMAX];
__device__ unsigned int g_ap_bits[NMAX];
__device__ unsigned int g_an_bits[NMAX];
__device__ int          g_is64;
__device__ __nv_bfloat162 g_Xb[NMAX * DD / 2];   // big terms
__device__ __nv_bfloat162 g_Xs[NMAX * DD / 2];   // small (residual) terms

// ---------------- SMEM layout (bytes) ----------------
#define SM_ABIG   0
#define SM_ASMALL (SM_ABIG   + 128 * LDA * 2)        // 34816
#define SM_BBIG   (SM_ASMALL + 128 * LDA * 2)        // 69632
#define SM_BSMALL (SM_BBIG   + 128 * LDA * 2)        // 104448
#define SM_C      SM_BBIG                            // C reuses B (68KB >= 67.6KB)
#define SM_SQ     (SM_BSMALL + 128 * LDA * 2)        // 139264
#define SM_LB     (SM_SQ + 512)
#define SM_TOTAL  (SM_LB + 512)

// ---------------------------------------------------------------------------
__global__ void detect_kernel(const int* __restrict__ T32, int n) {
    __shared__ int any_odd;
    if (threadIdx.x == 0) any_odd = 0;
    __syncthreads();
    int local = 0;
    for (int i = 1 + 2 * threadIdx.x; i < n; i += 2 * blockDim.x) local |= T32[i];
    if (local) atomicOr(&any_odd, 1);
    __syncthreads();
    if (threadIdx.x == 0) g_is64 = (any_odd == 0) ? 1 : 0;
}

// norms + labels + per-row atomic-combine init (reinit every launch)
__global__ void prep_kernel(const float* __restrict__ X,
                            const int* __restrict__ T32, int n) {
    int warp = (blockIdx.x * blockDim.x + threadIdx.x) >> 5;
    int lane = threadIdx.x & 31;
    if (warp >= n) return;
    float4 v = reinterpret_cast<const float4*>(X)[(size_t)warp * 32 + lane];
    float s = v.x * v.x + v.y * v.y + v.z * v.z + v.w * v.w;
#pragma unroll
    for (int o = 16; o; o >>= 1) s += __shfl_xor_sync(0xffffffffu, s, o);
    if (lane == 0) {
        g_sq[warp]      = s;
        g_lbl[warp]     = g_is64 ? T32[2 * warp] : T32[warp];
        g_ap_bits[warp] = 0u;
        g_an_bits[warp] = 0x7F7FFFFFu;  // FLT_MAX
    }
}

// bf16 2-term split: x = b0 + b1 (+ O(2^-18))
__global__ void split_kernel(const float* __restrict__ X, int n) {
    int i = blockIdx.x * blockDim.x + threadIdx.x;
    if (i >= n * (DD / 4)) return;
    float4 v = reinterpret_cast<const float4*>(X)[i];
    float xs[4] = {v.x, v.y, v.z, v.w};
    __nv_bfloat16 hb[4], hs[4];
#pragma unroll
    for (int j = 0; j < 4; j++) {
        hb[j] = __float2bfloat16(xs[j]);
        hs[j] = __float2bfloat16(xs[j] - __bfloat162float(hb[j]));
    }
    g_Xb[2 * i]     = __halves2bfloat162(hb[0], hb[1]);
    g_Xb[2 * i + 1] = __halves2bfloat162(hb[2], hb[3]);
    g_Xs[2 * i]     = __halves2bfloat162(hs[0], hs[1]);
    g_Xs[2 * i + 1] = __halves2bfloat162(hs[2], hs[3]);
}

// ---------------------------------------------------------------------------
// Main: WMMA bf16x3 Gram tiles (128 rows x 128 cols) + fused mining.
// grid = (n/128) rowblocks x 2 colhalves; 256 threads = 8 warps (2x4 tile).
// ---------------------------------------------------------------------------
__global__ void __launch_bounds__(256, 1)
triplet_wmma(int n) {
    extern __shared__ char smem[];
    const int tid = threadIdx.x;
    const int wid = tid >> 5;

    const int rb = blockIdx.x >> 1;           // row block
    const int ch = blockIdx.x & 1;            // col half
    const int rbase  = rb * 128;
    const int cstart = ch * (n >> 1);
    const int ntiles = n >> 8;                // 128-col tiles per half

    __nv_bfloat16* Abg = reinterpret_cast<__nv_bfloat16*>(smem + SM_ABIG);
    __nv_bfloat16* Asm = reinterpret_cast<__nv_bfloat16*>(smem + SM_ASMALL);
    __nv_bfloat16* Bbg = reinterpret_cast<__nv_bfloat16*>(smem + SM_BBIG);
    __nv_bfloat16* Bsm = reinterpret_cast<__nv_bfloat16*>(smem + SM_BSMALL);
    float*         Cs  = reinterpret_cast<float*>(smem + SM_C);
    float*         sqS = reinterpret_cast<float*>(smem + SM_SQ);
    int*           lbS = reinterpret_cast<int*>(smem + SM_LB);

    // ---- load A tiles (once): 128 rows x 128 bf16, big+small, padded ----
    {
        const uint4* Ab = reinterpret_cast<const uint4*>(g_Xb);
        const uint4* As = reinterpret_cast<const uint4*>(g_Xs);
#pragma unroll
        for (int e = tid; e < 128 * 16; e += 256) {
            int r = e >> 4, cq = e & 15;       // cq: 8-bf16 chunk
            uint4 vb = Ab[(size_t)(rbase + r) * 16 + cq];
            uint4 vs = As[(size_t)(rbase + r) * 16 + cq];
            *reinterpret_cast<uint4*>(&Abg[r * LDA + cq * 8]) = vb;
            *reinterpret_cast<uint4*>(&Asm[r * LDA + cq * 8]) = vs;
        }
    }

    const int   row  = tid >> 1;              // this thread's C row (0..127)
    const int   half = tid & 1;               // which 64-col half it mines
    const int   grow = rbase + row;
    const float sqA  = g_sq[grow];
    const int   lbA  = g_lbl[grow];
    float ap2 = -1e30f, an2 = 3e38f;

    const int warp_m = wid >> 2;              // 0..1
    const int warp_n = wid & 3;               // 0..3

    for (int t = 0; t < ntiles; t++) {
        const int cbase = cstart + t * 128;
        __syncthreads();  // prior mining reads of Cs done before B/C overwrite
                          // (also orders A fill before first MMA)

        // ---- load B tile: 128 cols x 128 bf16, big+small ----
        {
            const uint4* Bb = reinterpret_cast<const uint4*>(g_Xb);
            const uint4* Bs = reinterpret_cast<const uint4*>(g_Xs);
#pragma unroll
            for (int e = tid; e < 128 * 16; e += 256) {
                int c = e >> 4, cq = e & 15;
                uint4 vb = Bb[(size_t)(cbase + c) * 16 + cq];
                uint4 vs = Bs[(size_t)(cbase + c) * 16 + cq];
                *reinterpret_cast<uint4*>(&Bbg[c * LDA + cq * 8]) = vb;
                *reinterpret_cast<uint4*>(&Bsm[c * LDA + cq * 8]) = vs;
            }
        }
        if (tid < 128) {
            sqS[tid] = g_sq[cbase + tid];
            lbS[tid] = g_lbl[cbase + tid];
        }
        __syncthreads();

        // ---- 3-pass WMMA: b0b0 + b1b0 + b0b1 ----
        wmma::fragment<wmma::accumulator, 16, 16, 16, float> cf[4][2];
#pragma unroll
        for (int i = 0; i < 4; i++)
#pragma unroll
            for (int j = 0; j < 2; j++) wmma::fill_fragment(cf[i][j], 0.0f);

#pragma unroll
        for (int pass = 0; pass < 3; pass++) {
            const __nv_bfloat16* Ap = (pass == 1) ? Asm : Abg;
            const __nv_bfloat16* Bp = (pass == 2) ? Bsm : Bbg;
#pragma unroll
            for (int kc = 0; kc < 8; kc++) {
                wmma::fragment<wmma::matrix_a, 16, 16, 16, __nv_bfloat16,
                               wmma::row_major> af[4];
                wmma::fragment<wmma::matrix_b, 16, 16, 16, __nv_bfloat16,
                               wmma::col_major> bf[2];
#pragma unroll
                for (int i = 0; i < 4; i++)
                    wmma::load_matrix_sync(
                        af[i], Ap + (warp_m * 64 + i * 16) * LDA + kc * 16, LDA);
#pragma unroll
                for (int j = 0; j < 2; j++)
                    wmma::load_matrix_sync(
                        bf[j], Bp + (warp_n * 32 + j * 16) * LDA + kc * 16, LDA);
#pragma unroll
                for (int i = 0; i < 4; i++)
#pragma unroll
                    for (int j = 0; j < 2; j++)
                        wmma::mma_sync(cf[i][j], af[i], bf[j], cf[i][j]);
            }
        }

        __syncthreads();  // all B reads done before C overwrites B region
#pragma unroll
        for (int i = 0; i < 4; i++)
#pragma unroll
            for (int j = 0; j < 2; j++)
                wmma::store_matrix_sync(
                    Cs + (warp_m * 64 + i * 16) * LDC + warp_n * 32 + j * 16,
                    cf[i][j], LDC, wmma::mem_row_major);
        __syncthreads();

        // ---- mine: 2 threads per row, 64 cols each (float4 reads) ----
        {
            const float4* crow = reinterpret_cast<const float4*>(
                Cs + row * LDC + half * 64);
            const int cb = half * 64;
#pragma unroll
            for (int q = 0; q < 16; q++) {
                float4 v = crow[q];
                float d2;
                d2 = sqA + sqS[cb + 4 * q + 0] - 2.0f * v.x;
                if (lbS[cb + 4 * q + 0] == lbA) ap2 = fmaxf(ap2, d2);
                else                            an2 = fminf(an2, d2);
                d2 = sqA + sqS[cb + 4 * q + 1] - 2.0f * v.y;
                if (lbS[cb + 4 * q + 1] == lbA) ap2 = fmaxf(ap2, d2);
                else                            an2 = fminf(an2, d2);
                d2 = sqA + sqS[cb + 4 * q + 2] - 2.0f * v.z;
                if (lbS[cb + 4 * q + 2] == lbA) ap2 = fmaxf(ap2, d2);
                else                            an2 = fminf(an2, d2);
                d2 = sqA + sqS[cb + 4 * q + 3] - 2.0f * v.w;
                if (lbS[cb + 4 * q + 3] == lbA) ap2 = fmaxf(ap2, d2);
                else                            an2 = fminf(an2, d2);
            }
        }
    }

    // combine the two threads of each row (adjacent lanes), then col-halves
    ap2 = fmaxf(ap2, __shfl_xor_sync(0xffffffffu, ap2, 1));
    an2 = fminf(an2, __shfl_xor_sync(0xffffffffu, an2, 1));
    if (half == 0) {
        atomicMax(&g_ap_bits[grow], __float_as_uint(fmaxf(ap2, 0.0f)));
        atomicMin(&g_an_bits[grow], __float_as_uint(fmaxf(an2, 0.0f)));
    }
}

// ---------------------------------------------------------------------------
__global__ void triplet_final(float* __restrict__ out, int n, int out_size) {
    __shared__ float sL[256], sP[256];
    int tid = threadIdx.x;
    float ls = 0.f, ps = 0.f;
    for (int i = tid; i < n; i += 256) {
        float ap = sqrtf(fmaxf(__uint_as_float(g_ap_bits[i]), 1e-12f));
        float an = sqrtf(fmaxf(__uint_as_float(g_an_bits[i]), 1e-12f));
        ls += fmaxf(0.0f, 0.3f - (an - ap));
        ps += (an > ap) ? 1.0f : 0.0f;
    }
    sL[tid] = ls; sP[tid] = ps;
    __syncthreads();
    for (int s = 128; s; s >>= 1) {
        if (tid < s) { sL[tid] += sL[tid + s]; sP[tid] += sP[tid + s]; }
        __syncthreads();
    }
    if (tid == 0) {
        out[0] = sL[0] / (float)n;
        if (out_size > 1) out[1] = sP[0] / (float)n;
    }
    for (int i = 2 + tid; i < out_size; i += 256) out[i] = 0.0f;
}

// ---------------------------------------------------------------------------
extern "C" void kernel_launch(void* const* d_in, const int* in_sizes, int n_in,
                              void* d_out, int out_size) {
    const float* X   = (const float*)d_in[0];
    const int*   T32 = (const int*)d_in[1];
    int n = in_sizes[1];                 // 8192 labels (d fixed at 128)

    detect_kernel<<<1, 256>>>(T32, n);
    prep_kernel<<<(n + 7) / 8, 256>>>(X, T32, n);
    split_kernel<<<(n * (DD / 4) + 255) / 256, 256>>>(X, n);

    cudaFuncSetAttribute(triplet_wmma,
                         cudaFuncAttributeMaxDynamicSharedMemorySize, SM_TOTAL);
    triplet_wmma<<<(n >> 7) * 2, 256, SM_TOTAL>>>(n);

    triplet_final<<<1, 256>>>((float*)d_out, n, out_size);
}

// round 8
// speedup vs baseline: 2.7439x; 1.1311x over previous
#include <cuda_runtime.h>
#include <cuda_bf16.h>
#include <mma.h>
#include <cstdint>

using namespace nvcuda;

#define NMAX 8192
#define DD   128
#define LDA  136   // bf16 elems per smem row (pad kills LDSM conflicts)
#define LDC  68    // f32 elems per C row (64 + 4 pad)

__device__ float        g_sq[NMAX];
__device__ int          g_lbl[NMAX];
__device__ unsigned int g_ap_bits[NMAX];
__device__ unsigned int g_an_bits[NMAX];
__device__ int          g_is64;
__device__ __nv_bfloat162 g_Xb[NMAX * DD / 2];   // big terms
__device__ __nv_bfloat162 g_Xs[NMAX * DD / 2];   // small (residual) terms

// ---------------- SMEM layout (bytes) ----------------
// A big/small: 128 rows x LDA ; B big/small: 64 rows x LDA ; C overlays B.
#define SM_ABIG   0
#define SM_ASMALL (SM_ABIG   + 128 * LDA * 2)        // 34816
#define SM_BBIG   (SM_ASMALL + 128 * LDA * 2)        // 69632
#define SM_BSMALL (SM_BBIG   + 64 * LDA * 2)         // 87040
#define SM_C      SM_BBIG                            // 128*68*4 = 34816 = B big+small
#define SM_SQ     (SM_BSMALL + 64 * LDA * 2)         // 104448
#define SM_LB     (SM_SQ + 256)
#define SM_TOTAL  (SM_LB + 256)                      // ~105 KB -> 2 CTAs/SM

// ---------------------------------------------------------------------------
__global__ void detect_kernel(const int* __restrict__ T32, int n) {
    __shared__ int any_odd;
    if (threadIdx.x == 0) any_odd = 0;
    __syncthreads();
    int local = 0;
    for (int i = 1 + 2 * threadIdx.x; i < n; i += 2 * blockDim.x) local |= T32[i];
    if (local) atomicOr(&any_odd, 1);
    __syncthreads();
    if (threadIdx.x == 0) g_is64 = (any_odd == 0) ? 1 : 0;
}

// norms + labels + per-row atomic-combine init (reinit every launch)
__global__ void prep_kernel(const float* __restrict__ X,
                            const int* __restrict__ T32, int n) {
    int warp = (blockIdx.x * blockDim.x + threadIdx.x) >> 5;
    int lane = threadIdx.x & 31;
    if (warp >= n) return;
    float4 v = reinterpret_cast<const float4*>(X)[(size_t)warp * 32 + lane];
    float s = v.x * v.x + v.y * v.y + v.z * v.z + v.w * v.w;
#pragma unroll
    for (int o = 16; o; o >>= 1) s += __shfl_xor_sync(0xffffffffu, s, o);
    if (lane == 0) {
        g_sq[warp]      = s;
        g_lbl[warp]     = g_is64 ? T32[2 * warp] : T32[warp];
        g_ap_bits[warp] = 0u;
        g_an_bits[warp] = 0x7F7FFFFFu;  // FLT_MAX
    }
}

// bf16 2-term split: x = b0 + b1 (+ O(2^-18))
__global__ void split_kernel(const float* __restrict__ X, int n) {
    int i = blockIdx.x * blockDim.x + threadIdx.x;
    if (i >= n * (DD / 4)) return;
    float4 v = reinterpret_cast<const float4*>(X)[i];
    float xs[4] = {v.x, v.y, v.z, v.w};
    __nv_bfloat16 hb[4], hs[4];
#pragma unroll
    for (int j = 0; j < 4; j++) {
        hb[j] = __float2bfloat16(xs[j]);
        hs[j] = __float2bfloat16(xs[j] - __bfloat162float(hb[j]));
    }
    g_Xb[2 * i]     = __halves2bfloat162(hb[0], hb[1]);
    g_Xb[2 * i + 1] = __halves2bfloat162(hb[2], hb[3]);
    g_Xs[2 * i]     = __halves2bfloat162(hs[0], hs[1]);
    g_Xs[2 * i + 1] = __halves2bfloat162(hs[2], hs[3]);
}

// ---------------------------------------------------------------------------
// Main: WMMA bf16x3 Gram tiles (128 rows x 64 cols) + fused mining.
// grid = (n/128) rowblocks x 4 colquarters; 256 threads = 8 warps (4x2 tile).
// kc-outer fragment schedule: 8 fragment loads -> 12 MMAs (3 passes fused).
// ---------------------------------------------------------------------------
__global__ void __launch_bounds__(256, 2)
triplet_wmma(int n) {
    extern __shared__ char smem[];
    const int tid = threadIdx.x;
    const int wid = tid >> 5;

    const int rb = blockIdx.x >> 2;           // row block
    const int cq = blockIdx.x & 3;            // col quarter
    const int rbase  = rb * 128;
    const int cstart = cq * (n >> 2);
    const int ntiles = n >> 8;                // 64-col tiles per quarter

    __nv_bfloat16* Abg = reinterpret_cast<__nv_bfloat16*>(smem + SM_ABIG);
    __nv_bfloat16* Asm = reinterpret_cast<__nv_bfloat16*>(smem + SM_ASMALL);
    __nv_bfloat16* Bbg = reinterpret_cast<__nv_bfloat16*>(smem + SM_BBIG);
    __nv_bfloat16* Bsm = reinterpret_cast<__nv_bfloat16*>(smem + SM_BSMALL);
    float*         Cs  = reinterpret_cast<float*>(smem + SM_C);
    float*         sqS = reinterpret_cast<float*>(smem + SM_SQ);
    int*           lbS = reinterpret_cast<int*>(smem + SM_LB);

    // ---- load A tiles (once): 128 rows x 128 bf16, big+small ----
    {
        const uint4* Ab = reinterpret_cast<const uint4*>(g_Xb);
        const uint4* As = reinterpret_cast<const uint4*>(g_Xs);
#pragma unroll
        for (int e = tid; e < 128 * 16; e += 256) {
            int r = e >> 4, c8 = e & 15;
            uint4 vb = Ab[(size_t)(rbase + r) * 16 + c8];
            uint4 vs = As[(size_t)(rbase + r) * 16 + c8];
            *reinterpret_cast<uint4*>(&Abg[r * LDA + c8 * 8]) = vb;
            *reinterpret_cast<uint4*>(&Asm[r * LDA + c8 * 8]) = vs;
        }
    }

    const int   row  = tid >> 1;              // this thread's C row (0..127)
    const int   half = tid & 1;               // which 32-col half it mines
    const int   grow = rbase + row;
    const float sqA  = g_sq[grow];
    const int   lbA  = g_lbl[grow];
    float ap2 = -1e30f, an2 = 3e38f;

    const int warp_m = wid & 3;               // 0..3 -> 32-row band
    const int warp_n = wid >> 2;              // 0..1 -> 32-col band

    for (int t = 0; t < ntiles; t++) {
        const int cbase = cstart + t * 64;
        __syncthreads();  // prior mining reads of Cs done before B/C overwrite
                          // (also orders A fill before first MMA)

        // ---- load B tile: 64 cols x 128 bf16, big+small ----
        {
            const uint4* Bb = reinterpret_cast<const uint4*>(g_Xb);
            const uint4* Bs = reinterpret_cast<const uint4*>(g_Xs);
#pragma unroll
            for (int e = tid; e < 64 * 16; e += 256) {
                int c = e >> 4, c8 = e & 15;
                uint4 vb = Bb[(size_t)(cbase + c) * 16 + c8];
                uint4 vs = Bs[(size_t)(cbase + c) * 16 + c8];
                *reinterpret_cast<uint4*>(&Bbg[c * LDA + c8 * 8]) = vb;
                *reinterpret_cast<uint4*>(&Bsm[c * LDA + c8 * 8]) = vs;
            }
        }
        if (tid < 64) {
            sqS[tid] = g_sq[cbase + tid];
            lbS[tid] = g_lbl[cbase + tid];
        }
        __syncthreads();

        // ---- fused 3-pass WMMA, kc-outer fragment reuse ----
        wmma::fragment<wmma::accumulator, 16, 16, 16, float> cf[2][2];
#pragma unroll
        for (int i = 0; i < 2; i++)
#pragma unroll
            for (int j = 0; j < 2; j++) wmma::fill_fragment(cf[i][j], 0.0f);

#pragma unroll
        for (int kc = 0; kc < 8; kc++) {
            wmma::fragment<wmma::matrix_a, 16, 16, 16, __nv_bfloat16,
                           wmma::row_major> ab[2], as[2];
            wmma::fragment<wmma::matrix_b, 16, 16, 16, __nv_bfloat16,
                           wmma::col_major> bb[2], bs[2];
#pragma unroll
            for (int i = 0; i < 2; i++) {
                wmma::load_matrix_sync(
                    ab[i], Abg + (warp_m * 32 + i * 16) * LDA + kc * 16, LDA);
                wmma::load_matrix_sync(
                    as[i], Asm + (warp_m * 32 + i * 16) * LDA + kc * 16, LDA);
            }
#pragma unroll
            for (int j = 0; j < 2; j++) {
                wmma::load_matrix_sync(
                    bb[j], Bbg + (warp_n * 32 + j * 16) * LDA + kc * 16, LDA);
                wmma::load_matrix_sync(
                    bs[j], Bsm + (warp_n * 32 + j * 16) * LDA + kc * 16, LDA);
            }
#pragma unroll
            for (int i = 0; i < 2; i++)
#pragma unroll
                for (int j = 0; j < 2; j++) {
                    wmma::mma_sync(cf[i][j], ab[i], bb[j], cf[i][j]);
                    wmma::mma_sync(cf[i][j], as[i], bb[j], cf[i][j]);
                    wmma::mma_sync(cf[i][j], ab[i], bs[j], cf[i][j]);
                }
        }

        __syncthreads();  // all B fragment reads done before C overwrites B
#pragma unroll
        for (int i = 0; i < 2; i++)
#pragma unroll
            for (int j = 0; j < 2; j++)
                wmma::store_matrix_sync(
                    Cs + (warp_m * 32 + i * 16) * LDC + warp_n * 32 + j * 16,
                    cf[i][j], LDC, wmma::mem_row_major);
        __syncthreads();

        // ---- mine: 2 threads per row, 32 cols each (float4 reads) ----
        {
            const float4* crow = reinterpret_cast<const float4*>(
                Cs + row * LDC + half * 32);
            const int cb = half * 32;
#pragma unroll
            for (int q = 0; q < 8; q++) {
                float4 v = crow[q];
                float d2;
                d2 = sqA + sqS[cb + 4 * q + 0] - 2.0f * v.x;
                if (lbS[cb + 4 * q + 0] == lbA) ap2 = fmaxf(ap2, d2);
                else                            an2 = fminf(an2, d2);
                d2 = sqA + sqS[cb + 4 * q + 1] - 2.0f * v.y;
                if (lbS[cb + 4 * q + 1] == lbA) ap2 = fmaxf(ap2, d2);
                else                            an2 = fminf(an2, d2);
                d2 = sqA + sqS[cb + 4 * q + 2] - 2.0f * v.z;
                if (lbS[cb + 4 * q + 2] == lbA) ap2 = fmaxf(ap2, d2);
                else                            an2 = fminf(an2, d2);
                d2 = sqA + sqS[cb + 4 * q + 3] - 2.0f * v.w;
                if (lbS[cb + 4 * q + 3] == lbA) ap2 = fmaxf(ap2, d2);
                else                            an2 = fminf(an2, d2);
            }
        }
    }

    // combine row-halves (adjacent lanes), then col-quarters via atomics
    ap2 = fmaxf(ap2, __shfl_xor_sync(0xffffffffu, ap2, 1));
    an2 = fminf(an2, __shfl_xor_sync(0xffffffffu, an2, 1));
    if (half == 0) {
        atomicMax(&g_ap_bits[grow], __float_as_uint(fmaxf(ap2, 0.0f)));
        atomicMin(&g_an_bits[grow], __float_as_uint(fmaxf(an2, 0.0f)));
    }
}

// ---------------------------------------------------------------------------
__global__ void triplet_final(float* __restrict__ out, int n, int out_size) {
    __shared__ float sL[256], sP[256];
    int tid = threadIdx.x;
    float ls = 0.f, ps = 0.f;
    for (int i = tid; i < n; i += 256) {
        float ap = sqrtf(fmaxf(__uint_as_float(g_ap_bits[i]), 1e-12f));
        float an = sqrtf(fmaxf(__uint_as_float(g_an_bits[i]), 1e-12f));
        ls += fmaxf(0.0f, 0.3f - (an - ap));
        ps += (an > ap) ? 1.0f : 0.0f;
    }
    sL[tid] = ls; sP[tid] = ps;
    __syncthreads();
    for (int s = 128; s; s >>= 1) {
        if (tid < s) { sL[tid] += sL[tid + s]; sP[tid] += sP[tid + s]; }
        __syncthreads();
    }
    if (tid == 0) {
        out[0] = sL[0] / (float)n;
        if (out_size > 1) out[1] = sP[0] / (float)n;
    }
    for (int i = 2 + tid; i < out_size; i += 256) out[i] = 0.0f;
}

// ---------------------------------------------------------------------------
extern "C" void kernel_launch(void* const* d_in, const int* in_sizes, int n_in,
                              void* d_out, int out_size) {
    const float* X   = (const float*)d_in[0];
    const int*   T32 = (const int*)d_in[1];
    int n = in_sizes[1];                 // 8192 labels (d fixed at 128)

    detect_kernel<<<1, 256>>>(T32, n);
    prep_kernel<<<(n + 7) / 8, 256>>>(X, T32, n);
    split_kernel<<<(n * (DD / 4) + 255) / 256, 256>>>(X, n);

    cudaFuncSetAttribute(triplet_wmma,
                         cudaFuncAttributeMaxDynamicSharedMemorySize, SM_TOTAL);
    triplet_wmma<<<(n >> 7) * 4, 256, SM_TOTAL>>>(n);

    triplet_final<<<1, 256>>>((float*)d_out, n, out_size);
}

// round 9
// speedup vs baseline: 3.6559x; 1.3324x over previous
#include <cuda_runtime.h>
#include <cuda_bf16.h>
#include <cstdint>

#define NMAX 8192
#define DD   128
#define LDA  136   // bf16 elems per smem row (16B-pad: conflict-free ldmatrix)

__device__ float        g_sq[NMAX];
__device__ int          g_lbl[NMAX];
__device__ unsigned int g_ap_bits[NMAX];
__device__ unsigned int g_an_bits[NMAX];
__device__ int          g_is64;
__device__ __nv_bfloat162 g_Xb[NMAX * DD / 2];   // big terms
__device__ __nv_bfloat162 g_Xs[NMAX * DD / 2];   // small (residual) terms

// ---------------- SMEM layout (bytes) ----------------
#define SM_ABIG   0
#define SM_ASMALL (SM_ABIG   + 128 * LDA * 2)        // 34816
#define SM_BBIG   (SM_ASMALL + 128 * LDA * 2)        // 69632
#define SM_BSMALL (SM_BBIG   + 64 * LDA * 2)         // 87040
#define SM_SQ     (SM_BSMALL + 64 * LDA * 2)         // 104448
#define SM_LB     (SM_SQ + 256)
#define SM_TOTAL  (SM_LB + 256)                      // ~105 KB -> 2 CTAs/SM

// ---------------- PTX helpers ----------------
__device__ __forceinline__ uint32_t smem_u32(const void* p) {
    return (uint32_t)__cvta_generic_to_shared(p);
}
#define LDM_X4(r, a)                                                        \
    asm volatile("ldmatrix.sync.aligned.m8n8.x4.shared.b16 {%0,%1,%2,%3}, [%4];" \
                 : "=r"((r)[0]), "=r"((r)[1]), "=r"((r)[2]), "=r"((r)[3])   \
                 : "r"(a))
#define MMA16816(c, a, b0v, b1v)                                            \
    asm volatile("mma.sync.aligned.m16n8k16.row.col.f32.bf16.bf16.f32 "     \
                 "{%0,%1,%2,%3}, {%4,%5,%6,%7}, {%8,%9}, {%0,%1,%2,%3};"    \
                 : "+f"((c)[0]), "+f"((c)[1]), "+f"((c)[2]), "+f"((c)[3])   \
                 : "r"((a)[0]), "r"((a)[1]), "r"((a)[2]), "r"((a)[3]),      \
                   "r"(b0v), "r"(b1v))

// ---------------------------------------------------------------------------
__global__ void detect_kernel(const int* __restrict__ T32, int n) {
    __shared__ int any_odd;
    if (threadIdx.x == 0) any_odd = 0;
    __syncthreads();
    int local = 0;
    for (int i = 1 + 2 * threadIdx.x; i < n; i += 2 * blockDim.x) local |= T32[i];
    if (local) atomicOr(&any_odd, 1);
    __syncthreads();
    if (threadIdx.x == 0) g_is64 = (any_odd == 0) ? 1 : 0;
}

// norms + labels + per-row atomic-combine init (reinit every launch)
__global__ void prep_kernel(const float* __restrict__ X,
                            const int* __restrict__ T32, int n) {
    int warp = (blockIdx.x * blockDim.x + threadIdx.x) >> 5;
    int lane = threadIdx.x & 31;
    if (warp >= n) return;
    float4 v = reinterpret_cast<const float4*>(X)[(size_t)warp * 32 + lane];
    float s = v.x * v.x + v.y * v.y + v.z * v.z + v.w * v.w;
#pragma unroll
    for (int o = 16; o; o >>= 1) s += __shfl_xor_sync(0xffffffffu, s, o);
    if (lane == 0) {
        g_sq[warp]      = s;
        g_lbl[warp]     = g_is64 ? T32[2 * warp] : T32[warp];
        g_ap_bits[warp] = 0u;
        g_an_bits[warp] = 0x7F7FFFFFu;  // FLT_MAX
    }
}

// bf16 2-term split: x = b0 + b1 (+ O(2^-18))
__global__ void split_kernel(const float* __restrict__ X, int n) {
    int i = blockIdx.x * blockDim.x + threadIdx.x;
    if (i >= n * (DD / 4)) return;
    float4 v = reinterpret_cast<const float4*>(X)[i];
    float xs[4] = {v.x, v.y, v.z, v.w};
    __nv_bfloat16 hb[4], hs[4];
#pragma unroll
    for (int j = 0; j < 4; j++) {
        hb[j] = __float2bfloat16(xs[j]);
        hs[j] = __float2bfloat16(xs[j] - __bfloat162float(hb[j]));
    }
    g_Xb[2 * i]     = __halves2bfloat162(hb[0], hb[1]);
    g_Xb[2 * i + 1] = __halves2bfloat162(hb[2], hb[3]);
    g_Xs[2 * i]     = __halves2bfloat162(hs[0], hs[1]);
    g_Xs[2 * i + 1] = __halves2bfloat162(hs[2], hs[3]);
}

// ---------------------------------------------------------------------------
// Main: mma.sync bf16x3 Gram (128 rows x 64 cols per tile), register mining.
// grid = (n/128) rowblocks x 4 colquarters; 256 thr = 8 warps (4x2 warpgrid),
// warp tile m32n32 = 2 m-tiles x 4 n-tiles of m16n8k16.
// ---------------------------------------------------------------------------
__global__ void __launch_bounds__(256, 2)
triplet_mma(int n) {
    extern __shared__ char smem[];
    const int tid  = threadIdx.x;
    const int lane = tid & 31;
    const int wid  = tid >> 5;
    const int g    = lane >> 2;     // 0..7
    const int t4   = lane & 3;      // 0..3

    const int rb = blockIdx.x >> 2;
    const int cqd = blockIdx.x & 3;
    const int rbase  = rb * 128;
    const int cstart = cqd * (n >> 2);
    const int ntiles = n >> 8;       // 64-col tiles per quarter

    const int warp_m = wid & 3;      // 32-row band
    const int warp_n = wid >> 2;     // 32-col band

    __nv_bfloat16* Abg = reinterpret_cast<__nv_bfloat16*>(smem + SM_ABIG);
    __nv_bfloat16* Asm = reinterpret_cast<__nv_bfloat16*>(smem + SM_ASMALL);
    __nv_bfloat16* Bbg = reinterpret_cast<__nv_bfloat16*>(smem + SM_BBIG);
    __nv_bfloat16* Bsm = reinterpret_cast<__nv_bfloat16*>(smem + SM_BSMALL);
    float*         sqS = reinterpret_cast<float*>(smem + SM_SQ);
    int*           lbS = reinterpret_cast<int*>(smem + SM_LB);

    // ---- load A tiles (once): 128 rows x 128 bf16, big+small ----
    {
        const uint4* Ab = reinterpret_cast<const uint4*>(g_Xb);
        const uint4* As = reinterpret_cast<const uint4*>(g_Xs);
#pragma unroll
        for (int e = tid; e < 128 * 16; e += 256) {
            int r = e >> 4, c8 = e & 15;
            uint4 vb = Ab[(size_t)(rbase + r) * 16 + c8];
            uint4 vs = As[(size_t)(rbase + r) * 16 + c8];
            *reinterpret_cast<uint4*>(&Abg[r * LDA + c8 * 8]) = vb;
            *reinterpret_cast<uint4*>(&Asm[r * LDA + c8 * 8]) = vs;
        }
    }

    // ---- ldmatrix lane addressing ----
    const int sub = lane >> 3, rw = lane & 7;
    // A atoms: sub0=(m0,k0)->a0, sub1=(m8,k0)->a1, sub2=(m0,k8)->a2, sub3=(m8,k8)->a3
    uint32_t aAb[2], aAs[2];
#pragma unroll
    for (int mt = 0; mt < 2; mt++) {
        int row = warp_m * 32 + mt * 16 + (sub & 1) * 8 + rw;
        int col = (sub >> 1) * 8;
        aAb[mt] = smem_u32(&Abg[row * LDA + col]);
        aAs[mt] = smem_u32(&Asm[row * LDA + col]);
    }
    // B atoms: sub0=(n0,k0)->b0, sub1=(n0,k8)->b1, sub2=(n8,k0), sub3=(n8,k8)
    uint32_t aBb[2], aBs[2];
#pragma unroll
    for (int bl = 0; bl < 2; bl++) {
        int row = warp_n * 32 + bl * 16 + (sub >> 1) * 8 + rw;
        int col = (sub & 1) * 8;
        aBb[bl] = smem_u32(&Bbg[row * LDA + col]);
        aBs[bl] = smem_u32(&Bsm[row * LDA + col]);
    }

    // ---- per-thread fixed rows: s = mt*2 + h -> row = wm*32+mt*16+h*8+g ----
    float sqA[4]; int lbA[4]; int rowG[4];
    float ap2[4], an2[4];
#pragma unroll
    for (int s = 0; s < 4; s++) {
        int mt = s >> 1, h = s & 1;
        rowG[s] = rbase + warp_m * 32 + mt * 16 + h * 8 + g;
        sqA[s]  = g_sq[rowG[s]];
        lbA[s]  = g_lbl[rowG[s]];
        ap2[s]  = -1e30f;
        an2[s]  = 3e38f;
    }

    for (int tt = 0; tt < ntiles; tt++) {
        const int cbase = cstart + tt * 64;
        __syncthreads();   // prior tile's MMAs done before B refill
                           // (also orders A fill before first MMA)
        {
            const uint4* Bb = reinterpret_cast<const uint4*>(g_Xb);
            const uint4* Bs = reinterpret_cast<const uint4*>(g_Xs);
#pragma unroll
            for (int e = tid; e < 64 * 16; e += 256) {
                int c = e >> 4, c8 = e & 15;
                uint4 vb = Bb[(size_t)(cbase + c) * 16 + c8];
                uint4 vs = Bs[(size_t)(cbase + c) * 16 + c8];
                *reinterpret_cast<uint4*>(&Bbg[c * LDA + c8 * 8]) = vb;
                *reinterpret_cast<uint4*>(&Bsm[c * LDA + c8 * 8]) = vs;
            }
        }
        if (tid < 64) {
            sqS[tid] = g_sq[cbase + tid];
            lbS[tid] = g_lbl[cbase + tid];
        }
        __syncthreads();

        // ---- fused 3-pass mma.sync, kc-outer fragment reuse ----
        float acc[2][4][4];
#pragma unroll
        for (int mt = 0; mt < 2; mt++)
#pragma unroll
            for (int j = 0; j < 4; j++)
#pragma unroll
                for (int e = 0; e < 4; e++) acc[mt][j][e] = 0.0f;

#pragma unroll
        for (int kc = 0; kc < 8; kc++) {
            uint32_t Ab0[4], Ab1[4], As0[4], As1[4];
            uint32_t Bb0[4], Bb1[4], Bs0[4], Bs1[4];
            LDM_X4(Ab0, aAb[0] + kc * 32);
            LDM_X4(Ab1, aAb[1] + kc * 32);
            LDM_X4(As0, aAs[0] + kc * 32);
            LDM_X4(As1, aAs[1] + kc * 32);
            LDM_X4(Bb0, aBb[0] + kc * 32);
            LDM_X4(Bb1, aBb[1] + kc * 32);
            LDM_X4(Bs0, aBs[0] + kc * 32);
            LDM_X4(Bs1, aBs[1] + kc * 32);
            // B x4 result: {ntile0.b0, ntile0.b1, ntile1.b0, ntile1.b1}
#pragma unroll
            for (int mt = 0; mt < 2; mt++) {
                uint32_t* Ab = mt ? Ab1 : Ab0;
                uint32_t* As = mt ? As1 : As0;
#pragma unroll
                for (int j = 0; j < 4; j++) {
                    uint32_t* Bb = (j < 2) ? Bb0 : Bb1;
                    uint32_t* Bs = (j < 2) ? Bs0 : Bs1;
                    uint32_t b0b = Bb[(j & 1) * 2], b1b = Bb[(j & 1) * 2 + 1];
                    uint32_t b0s = Bs[(j & 1) * 2], b1s = Bs[(j & 1) * 2 + 1];
                    MMA16816(acc[mt][j], Ab, b0b, b1b);
                    MMA16816(acc[mt][j], As, b0b, b1b);
                    MMA16816(acc[mt][j], Ab, b0s, b1s);
                }
            }
        }

        // ---- register mining: thread cols = wn*32 + j*8 + 2t + e ----
        float sqC[8]; int lbC[8];
#pragma unroll
        for (int j = 0; j < 4; j++) {
#pragma unroll
            for (int e = 0; e < 2; e++) {
                int cl = warp_n * 32 + j * 8 + 2 * t4 + e;
                sqC[j * 2 + e] = sqS[cl];
                lbC[j * 2 + e] = lbS[cl];
            }
        }
#pragma unroll
        for (int mt = 0; mt < 2; mt++)
#pragma unroll
            for (int j = 0; j < 4; j++)
#pragma unroll
                for (int e = 0; e < 4; e++) {
                    int h = e >> 1, ec = e & 1;   // reg e: row h*8+g, col 2t+ec
                    int s = mt * 2 + h;
                    float d2 = sqA[s] + sqC[j * 2 + ec] - 2.0f * acc[mt][j][e];
                    if (lbC[j * 2 + ec] == lbA[s]) ap2[s] = fmaxf(ap2[s], d2);
                    else                           an2[s] = fminf(an2[s], d2);
                }
    }

    // ---- reduce over the 4 t-lanes sharing each row, then merge quarters ----
#pragma unroll
    for (int s = 0; s < 4; s++) {
        ap2[s] = fmaxf(ap2[s], __shfl_xor_sync(0xffffffffu, ap2[s], 1));
        ap2[s] = fmaxf(ap2[s], __shfl_xor_sync(0xffffffffu, ap2[s], 2));
        an2[s] = fminf(an2[s], __shfl_xor_sync(0xffffffffu, an2[s], 1));
        an2[s] = fminf(an2[s], __shfl_xor_sync(0xffffffffu, an2[s], 2));
    }
    if (t4 == 0) {
#pragma unroll
        for (int s = 0; s < 4; s++) {
            atomicMax(&g_ap_bits[rowG[s]], __float_as_uint(fmaxf(ap2[s], 0.0f)));
            atomicMin(&g_an_bits[rowG[s]], __float_as_uint(fmaxf(an2[s], 0.0f)));
        }
    }
}

// ---------------------------------------------------------------------------
__global__ void triplet_final(float* __restrict__ out, int n, int out_size) {
    __shared__ float sL[256], sP[256];
    int tid = threadIdx.x;
    float ls = 0.f, ps = 0.f;
    for (int i = tid; i < n; i += 256) {
        float ap = sqrtf(fmaxf(__uint_as_float(g_ap_bits[i]), 1e-12f));
        float an = sqrtf(fmaxf(__uint_as_float(g_an_bits[i]), 1e-12f));
        ls += fmaxf(0.0f, 0.3f - (an - ap));
        ps += (an > ap) ? 1.0f : 0.0f;
    }
    sL[tid] = ls; sP[tid] = ps;
    __syncthreads();
    for (int s = 128; s; s >>= 1) {
        if (tid < s) { sL[tid] += sL[tid + s]; sP[tid] += sP[tid + s]; }
        __syncthreads();
    }
    if (tid == 0) {
        out[0] = sL[0] / (float)n;
        if (out_size > 1) out[1] = sP[0] / (float)n;
    }
    for (int i = 2 + tid; i < out_size; i += 256) out[i] = 0.0f;
}

// ---------------------------------------------------------------------------
extern "C" void kernel_launch(void* const* d_in, const int* in_sizes, int n_in,
                              void* d_out, int out_size) {
    const float* X   = (const float*)d_in[0];
    const int*   T32 = (const int*)d_in[1];
    int n = in_sizes[1];                 // 8192 labels (d fixed at 128)

    detect_kernel<<<1, 256>>>(T32, n);
    prep_kernel<<<(n + 7) / 8, 256>>>(X, T32, n);
    split_kernel<<<(n * (DD / 4) + 255) / 256, 256>>>(X, n);

    cudaFuncSetAttribute(triplet_mma,
                         cudaFuncAttributeMaxDynamicSharedMemorySize, SM_TOTAL);
    triplet_mma<<<(n >> 7) * 4, 256, SM_TOTAL>>>(n);

    triplet_final<<<1, 256>>>((float*)d_out, n, out_size);
}

// round 11
// speedup vs baseline: 4.8946x; 1.3388x over previous
#include <cuda_runtime.h>
#include <cuda_bf16.h>
#include <cstdint>

#define NMAX 8192
#define DD   128
#define LDA  136   // bf16 elems per smem row (16B-pad: conflict-free ldmatrix)

__device__ float        g_sq[NMAX];
__device__ int          g_lbl[NMAX];
__device__ unsigned int g_ap_bits[NMAX];
__device__ unsigned int g_an_bits[NMAX];
__device__ int          g_is64;
__device__ __nv_bfloat162 g_Xb[NMAX * DD / 2];   // big terms
__device__ __nv_bfloat162 g_Xs[NMAX * DD / 2];   // small (residual) terms

// ---------------- SMEM layout (bytes) ----------------
#define SM_ABIG   0
#define SM_ASMALL (SM_ABIG   + 128 * LDA * 2)        // 34816
#define SM_BBIG   (SM_ASMALL + 128 * LDA * 2)        // 69632
#define SM_BSMALL (SM_BBIG   + 64 * LDA * 2)         // 87040
#define SM_SQ     (SM_BSMALL + 64 * LDA * 2)         // 104448
#define SM_LB     (SM_SQ + 256)
#define SM_TOTAL  (SM_LB + 256)                      // ~105 KB -> 2 CTAs/SM

// ---------------- PTX helpers ----------------
__device__ __forceinline__ uint32_t smem_u32(const void* p) {
    return (uint32_t)__cvta_generic_to_shared(p);
}
#define LDM_X4(r, a)                                                        \
    asm volatile("ldmatrix.sync.aligned.m8n8.x4.shared.b16 {%0,%1,%2,%3}, [%4];" \
                 : "=r"((r)[0]), "=r"((r)[1]), "=r"((r)[2]), "=r"((r)[3])   \
                 : "r"(a))
#define MMA16816(c, a, b0v, b1v)                                            \
    asm volatile("mma.sync.aligned.m16n8k16.row.col.f32.bf16.bf16.f32 "     \
                 "{%0,%1,%2,%3}, {%4,%5,%6,%7}, {%8,%9}, {%0,%1,%2,%3};"    \
                 : "+f"((c)[0]), "+f"((c)[1]), "+f"((c)[2]), "+f"((c)[3])   \
                 : "r"((a)[0]), "r"((a)[1]), "r"((a)[2]), "r"((a)[3]),      \
                   "r"(b0v), "r"(b1v))

// ---------------------------------------------------------------------------
__global__ void detect_kernel(const int* __restrict__ T32, int n) {
    __shared__ int any_odd;
    if (threadIdx.x == 0) any_odd = 0;
    __syncthreads();
    int local = 0;
    for (int i = 1 + 2 * threadIdx.x; i < n; i += 2 * blockDim.x) local |= T32[i];
    if (local) atomicOr(&any_odd, 1);
    __syncthreads();
    if (threadIdx.x == 0) g_is64 = (any_odd == 0) ? 1 : 0;
}

// norms + labels + per-row atomic-combine init (reinit every launch)
__global__ void prep_kernel(const float* __restrict__ X,
                            const int* __restrict__ T32, int n) {
    int warp = (blockIdx.x * blockDim.x + threadIdx.x) >> 5;
    int lane = threadIdx.x & 31;
    if (warp >= n) return;
    float4 v = reinterpret_cast<const float4*>(X)[(size_t)warp * 32 + lane];
    float s = v.x * v.x + v.y * v.y + v.z * v.z + v.w * v.w;
#pragma unroll
    for (int o = 16; o; o >>= 1) s += __shfl_xor_sync(0xffffffffu, s, o);
    if (lane == 0) {
        g_sq[warp]      = s;
        g_lbl[warp]     = g_is64 ? T32[2 * warp] : T32[warp];
        g_ap_bits[warp] = 0u;
        g_an_bits[warp] = 0x7F7FFFFFu;  // FLT_MAX
    }
}

// bf16 2-term split: x = b0 + b1 (+ O(2^-18))
__global__ void split_kernel(const float* __restrict__ X, int n) {
    int i = blockIdx.x * blockDim.x + threadIdx.x;
    if (i >= n * (DD / 4)) return;
    float4 v = reinterpret_cast<const float4*>(X)[i];
    float xs[4] = {v.x, v.y, v.z, v.w};
    __nv_bfloat16 hb[4], hs[4];
#pragma unroll
    for (int j = 0; j < 4; j++) {
        hb[j] = __float2bfloat16(xs[j]);
        hs[j] = __float2bfloat16(xs[j] - __bfloat162float(hb[j]));
    }
    g_Xb[2 * i]     = __halves2bfloat162(hb[0], hb[1]);
    g_Xb[2 * i + 1] = __halves2bfloat162(hb[2], hb[3]);
    g_Xs[2 * i]     = __halves2bfloat162(hs[0], hs[1]);
    g_Xs[2 * i + 1] = __halves2bfloat162(hs[2], hs[3]);
}

// ---------------------------------------------------------------------------
// Main: symmetric (upper-triangular) bf16x3 Gram + dual-side mining.
// Pair rowblocks (p, 63-p): exactly 130 64-col tiles -> 8 chunks/pair.
// grid = 32 pairs x 8 chunks = 256 CTAs; 8 warps; warp tile m32n32.
// ---------------------------------------------------------------------------
__global__ void __launch_bounds__(256, 2)
triplet_mma(int n) {
    extern __shared__ char smem[];
    const int tid  = threadIdx.x;
    const int lane = tid & 31;
    const int wid  = tid >> 5;
    const int g    = lane >> 2;     // 0..7
    const int t4   = lane & 3;      // 0..3

    const int nrb   = n >> 7;          // rowblocks (64)
    const int pairs = nrb >> 1;        // 32
    const int p  = blockIdx.x >> 3;    // pair id
    const int q  = blockIdx.x & 7;     // chunk id
    const int rbA = p;                 // first rowblock of pair
    const int rbB = nrb - 1 - p;       // second
    const int T1 = 2 * (nrb - rbA);    // tiles of rowblock A (cols >= 2*rbA)
    const int Ttot = T1 + 2 * (rbB - rbB + (p + 1));  // = 130 for n=8192
    const int s0 = (q * Ttot) >> 3;
    const int s1 = ((q + 1) * Ttot) >> 3;
    (void)pairs;

    const int warp_m = wid & 3;      // 32-row band
    const int warp_n = wid >> 2;     // 32-col band

    __nv_bfloat16* Abg = reinterpret_cast<__nv_bfloat16*>(smem + SM_ABIG);
    __nv_bfloat16* Asm = reinterpret_cast<__nv_bfloat16*>(smem + SM_ASMALL);
    __nv_bfloat16* Bbg = reinterpret_cast<__nv_bfloat16*>(smem + SM_BBIG);
    __nv_bfloat16* Bsm = reinterpret_cast<__nv_bfloat16*>(smem + SM_BSMALL);
    float*         sqS = reinterpret_cast<float*>(smem + SM_SQ);
    int*           lbS = reinterpret_cast<int*>(smem + SM_LB);

    // ---- ldmatrix lane addressing (smem-fixed) ----
    const int sub = lane >> 3, rw = lane & 7;
    uint32_t aAb[2], aAs[2];
#pragma unroll
    for (int mt = 0; mt < 2; mt++) {
        int row = warp_m * 32 + mt * 16 + (sub & 1) * 8 + rw;
        int col = (sub >> 1) * 8;
        aAb[mt] = smem_u32(&Abg[row * LDA + col]);
        aAs[mt] = smem_u32(&Asm[row * LDA + col]);
    }
    uint32_t aBb[2], aBs[2];
#pragma unroll
    for (int bl = 0; bl < 2; bl++) {
        int row = warp_n * 32 + bl * 16 + (sub >> 1) * 8 + rw;
        int col = (sub & 1) * 8;
        aBb[bl] = smem_u32(&Bbg[row * LDA + col]);
        aBs[bl] = smem_u32(&Bsm[row * LDA + col]);
    }

    float sqA[4]; int lbA[4]; int rowG[4];
    float ap2[4], an2[4];
    int loaded_rb = -1;

    for (int s = s0; s < s1; s++) {
        // tile -> (rowblock, col tile)
        int rb, ct;
        if (s < T1) { rb = rbA; ct = 2 * rbA + s; }
        else        { rb = rbB; ct = 2 * rbB + (s - T1); }
        const int rbase = rb << 7;
        const int cbase = ct << 6;

        __syncthreads();   // prior tile's MMAs/LDS done before smem refill

        if (rb != loaded_rb) {
            // flush + reset row stats of previous rowblock
            if (loaded_rb >= 0) {
#pragma unroll
                for (int ss = 0; ss < 4; ss++) {
                    ap2[ss] = fmaxf(ap2[ss], __shfl_xor_sync(0xffffffffu, ap2[ss], 1));
                    ap2[ss] = fmaxf(ap2[ss], __shfl_xor_sync(0xffffffffu, ap2[ss], 2));
                    an2[ss] = fminf(an2[ss], __shfl_xor_sync(0xffffffffu, an2[ss], 1));
                    an2[ss] = fminf(an2[ss], __shfl_xor_sync(0xffffffffu, an2[ss], 2));
                    if (t4 == 0) {
                        atomicMax(&g_ap_bits[rowG[ss]], __float_as_uint(fmaxf(ap2[ss], 0.0f)));
                        atomicMin(&g_an_bits[rowG[ss]], __float_as_uint(fmaxf(an2[ss], 0.0f)));
                    }
                }
            }
            // load A tiles for new rowblock
            {
                const uint4* Ab = reinterpret_cast<const uint4*>(g_Xb);
                const uint4* As = reinterpret_cast<const uint4*>(g_Xs);
#pragma unroll
                for (int e = tid; e < 128 * 16; e += 256) {
                    int r = e >> 4, c8 = e & 15;
                    uint4 vb = Ab[(size_t)(rbase + r) * 16 + c8];
                    uint4 vs = As[(size_t)(rbase + r) * 16 + c8];
                    *reinterpret_cast<uint4*>(&Abg[r * LDA + c8 * 8]) = vb;
                    *reinterpret_cast<uint4*>(&Asm[r * LDA + c8 * 8]) = vs;
                }
            }
#pragma unroll
            for (int ss = 0; ss < 4; ss++) {
                int mt = ss >> 1, h = ss & 1;
                rowG[ss] = rbase + warp_m * 32 + mt * 16 + h * 8 + g;
                sqA[ss]  = g_sq[rowG[ss]];
                lbA[ss]  = g_lbl[rowG[ss]];
                ap2[ss]  = -1e30f;
                an2[ss]  = 3e38f;
            }
            loaded_rb = rb;
        }

        // ---- load B tile: 64 cols x 128 bf16, big+small ----
        {
            const uint4* Bb = reinterpret_cast<const uint4*>(g_Xb);
            const uint4* Bs = reinterpret_cast<const uint4*>(g_Xs);
#pragma unroll
            for (int e = tid; e < 64 * 16; e += 256) {
                int c = e >> 4, c8 = e & 15;
                uint4 vb = Bb[(size_t)(cbase + c) * 16 + c8];
                uint4 vs = Bs[(size_t)(cbase + c) * 16 + c8];
                *reinterpret_cast<uint4*>(&Bbg[c * LDA + c8 * 8]) = vb;
                *reinterpret_cast<uint4*>(&Bsm[c * LDA + c8 * 8]) = vs;
            }
        }
        if (tid < 64) {
            sqS[tid] = g_sq[cbase + tid];
            lbS[tid] = g_lbl[cbase + tid];
        }
        __syncthreads();

        // ---- fused 3-pass mma.sync, kc-outer fragment reuse ----
        float acc[2][4][4];
#pragma unroll
        for (int mt = 0; mt < 2; mt++)
#pragma unroll
            for (int j = 0; j < 4; j++)
#pragma unroll
                for (int e = 0; e < 4; e++) acc[mt][j][e] = 0.0f;

#pragma unroll
        for (int kc = 0; kc < 8; kc++) {
            uint32_t Ab0[4], Ab1[4], As0[4], As1[4];
            uint32_t Bb0[4], Bb1[4], Bs0[4], Bs1[4];
            LDM_X4(Ab0, aAb[0] + kc * 32);
            LDM_X4(Ab1, aAb[1] + kc * 32);
            LDM_X4(As0, aAs[0] + kc * 32);
            LDM_X4(As1, aAs[1] + kc * 32);
            LDM_X4(Bb0, aBb[0] + kc * 32);
            LDM_X4(Bb1, aBb[1] + kc * 32);
            LDM_X4(Bs0, aBs[0] + kc * 32);
            LDM_X4(Bs1, aBs[1] + kc * 32);
#pragma unroll
            for (int mt = 0; mt < 2; mt++) {
                uint32_t* Ab = mt ? Ab1 : Ab0;
                uint32_t* As = mt ? As1 : As0;
#pragma unroll
                for (int j = 0; j < 4; j++) {
                    uint32_t* Bb = (j < 2) ? Bb0 : Bb1;
                    uint32_t* Bs = (j < 2) ? Bs0 : Bs1;
                    uint32_t b0b = Bb[(j & 1) * 2], b1b = Bb[(j & 1) * 2 + 1];
                    uint32_t b0s = Bs[(j & 1) * 2], b1s = Bs[(j & 1) * 2 + 1];
                    MMA16816(acc[mt][j], Ab, b0b, b1b);
                    MMA16816(acc[mt][j], As, b0b, b1b);
                    MMA16816(acc[mt][j], Ab, b0s, b1s);
                }
            }
        }

        // ---- dual-side register mining ----
        float sqC[8]; int lbC[8];
#pragma unroll
        for (int j = 0; j < 4; j++)
#pragma unroll
            for (int ec = 0; ec < 2; ec++) {
                int cl = warp_n * 32 + j * 8 + 2 * t4 + ec;
                sqC[j * 2 + ec] = sqS[cl];
                lbC[j * 2 + ec] = lbS[cl];
            }
#pragma unroll
        for (int j = 0; j < 4; j++)
#pragma unroll
            for (int ec = 0; ec < 2; ec++) {
                float cap = -1e30f, can = 3e38f;
#pragma unroll
                for (int mt = 0; mt < 2; mt++)
#pragma unroll
                    for (int h = 0; h < 2; h++) {
                        int ss = mt * 2 + h, e = h * 2 + ec;
                        float d2 = sqA[ss] + sqC[j * 2 + ec] - 2.0f * acc[mt][j][e];
                        if (lbC[j * 2 + ec] == lbA[ss]) {
                            ap2[ss] = fmaxf(ap2[ss], d2);
                            cap     = fmaxf(cap, d2);
                        } else {
                            an2[ss] = fminf(an2[ss], d2);
                            can     = fminf(can, d2);
                        }
                    }
                // col-side: reduce over g lanes (32 rows of this warp band)
                cap = fmaxf(cap, __shfl_xor_sync(0xffffffffu, cap, 4));
                cap = fmaxf(cap, __shfl_xor_sync(0xffffffffu, cap, 8));
                cap = fmaxf(cap, __shfl_xor_sync(0xffffffffu, cap, 16));
                can = fminf(can, __shfl_xor_sync(0xffffffffu, can, 4));
                can = fminf(can, __shfl_xor_sync(0xffffffffu, can, 8));
                can = fminf(can, __shfl_xor_sync(0xffffffffu, can, 16));
                if (g == 0) {
                    int c = cbase + warp_n * 32 + j * 8 + 2 * t4 + ec;
                    if (cap > -1e29f)
                        atomicMax(&g_ap_bits[c], __float_as_uint(fmaxf(cap, 0.0f)));
                    if (can < 1e38f)
                        atomicMin(&g_an_bits[c], __float_as_uint(fmaxf(can, 0.0f)));
                }
            }
    }

    // ---- final row-stat flush ----
    if (loaded_rb >= 0) {
#pragma unroll
        for (int ss = 0; ss < 4; ss++) {
            ap2[ss] = fmaxf(ap2[ss], __shfl_xor_sync(0xffffffffu, ap2[ss], 1));
            ap2[ss] = fmaxf(ap2[ss], __shfl_xor_sync(0xffffffffu, ap2[ss], 2));
            an2[ss] = fminf(an2[ss], __shfl_xor_sync(0xffffffffu, an2[ss], 1));
            an2[ss] = fminf(an2[ss], __shfl_xor_sync(0xffffffffu, an2[ss], 2));
            if (t4 == 0) {
                atomicMax(&g_ap_bits[rowG[ss]], __float_as_uint(fmaxf(ap2[ss], 0.0f)));
                atomicMin(&g_an_bits[rowG[ss]], __float_as_uint(fmaxf(an2[ss], 0.0f)));
            }
        }
    }
}

// ---------------------------------------------------------------------------
__global__ void triplet_final(float* __restrict__ out, int n, int out_size) {
    __shared__ float sL[256], sP[256];
    int tid = threadIdx.x;
    float ls = 0.f, ps = 0.f;
    for (int i = tid; i < n; i += 256) {
        float ap = sqrtf(fmaxf(__uint_as_float(g_ap_bits[i]), 1e-12f));
        float an = sqrtf(fmaxf(__uint_as_float(g_an_bits[i]), 1e-12f));
        ls += fmaxf(0.0f, 0.3f - (an - ap));
        ps += (an > ap) ? 1.0f : 0.0f;
    }
    sL[tid] = ls; sP[tid] = ps;
    __syncthreads();
    for (int s = 128; s; s >>= 1) {
        if (tid < s) { sL[tid] += sL[tid + s]; sP[tid] += sP[tid + s]; }
        __syncthreads();
    }
    if (tid == 0) {
        out[0] = sL[0] / (float)n;
        if (out_size > 1) out[1] = sP[0] / (float)n;
    }
    for (int i = 2 + tid; i < out_size; i += 256) out[i] = 0.0f;
}

// ---------------------------------------------------------------------------
extern "C" void kernel_launch(void* const* d_in, const int* in_sizes, int n_in,
                              void* d_out, int out_size) {
    const float* X   = (const float*)d_in[0];
    const int*   T32 = (const int*)d_in[1];
    int n = in_sizes[1];                 // 8192 labels (d fixed at 128)

    detect_kernel<<<1, 256>>>(T32, n);
    prep_kernel<<<(n + 7) / 8, 256>>>(X, T32, n);
    split_kernel<<<(n * (DD / 4) + 255) / 256, 256>>>(X, n);

    cudaFuncSetAttribute(triplet_mma,
                         cudaFuncAttributeMaxDynamicSharedMemorySize, SM_TOTAL);
    triplet_mma<<<(n >> 8) * 8, 256, SM_TOTAL>>>(n);   // 32 pairs x 8 chunks

    triplet_final<<<1, 256>>>((float*)d_out, n, out_size);
}

// round 12
// speedup vs baseline: 6.5562x; 1.3395x over previous
#include <cuda_runtime.h>
#include <cuda_bf16.h>
#include <cstdint>

#define NMAX 8192
#define DD   128
#define LDA  136   // bf16 elems per smem row (16B-pad: conflict-free ldmatrix)
#define CH   9     // chunks per pair -> grid = 32*9 = 288 = 2 x 144 SMs

__device__ float        g_sq[NMAX];
__device__ int          g_lbl[NMAX];
__device__ unsigned int g_ap_bits[NMAX];
__device__ unsigned int g_an_bits[NMAX];
__device__ __nv_bfloat162 g_Xb[NMAX * DD / 2];   // big terms
__device__ __nv_bfloat162 g_Xs[NMAX * DD / 2];   // small (residual) terms

// ---------------- SMEM layout (bytes) ----------------
#define SM_ABIG   0
#define SM_ASMALL (SM_ABIG   + 128 * LDA * 2)        // 34816
#define SM_BBIG   (SM_ASMALL + 128 * LDA * 2)        // 69632
#define SM_BSMALL (SM_BBIG   + 64 * LDA * 2)         // 87040
#define SM_SQ     (SM_BSMALL + 64 * LDA * 2)         // 104448
#define SM_LB     (SM_SQ + 256)
#define SM_TOTAL  (SM_LB + 256)                      // ~105 KB -> 2 CTAs/SM

// ---------------- PTX helpers ----------------
__device__ __forceinline__ uint32_t smem_u32(const void* p) {
    return (uint32_t)__cvta_generic_to_shared(p);
}
#define LDM_X4(r, a)                                                        \
    asm volatile("ldmatrix.sync.aligned.m8n8.x4.shared.b16 {%0,%1,%2,%3}, [%4];" \
                 : "=r"((r)[0]), "=r"((r)[1]), "=r"((r)[2]), "=r"((r)[3])   \
                 : "r"(a))
#define MMA16816(c, a, b0v, b1v)                                            \
    asm volatile("mma.sync.aligned.m16n8k16.row.col.f32.bf16.bf16.f32 "     \
                 "{%0,%1,%2,%3}, {%4,%5,%6,%7}, {%8,%9}, {%0,%1,%2,%3};"    \
                 : "+f"((c)[0]), "+f"((c)[1]), "+f"((c)[2]), "+f"((c)[3])   \
                 : "r"((a)[0]), "r"((a)[1]), "r"((a)[2]), "r"((a)[3]),      \
                   "r"(b0v), "r"(b1v))
#define CP16(dst, src)                                                      \
    asm volatile("cp.async.cg.shared.global [%0], [%1], 16;"                \
                 :: "r"(dst), "l"(src))
#define CP4(dst, src)                                                       \
    asm volatile("cp.async.ca.shared.global [%0], [%1], 4;"                 \
                 :: "r"(dst), "l"(src))
#define CP_COMMIT() asm volatile("cp.async.commit_group;")
#define CP_WAIT0()  asm volatile("cp.async.wait_group 0;" ::: "memory")

// ---------------------------------------------------------------------------
// Fused prep: label-layout detect (per block) + norms + labels + bf16 split
// + per-row atomic-init. grid = n*32/256 blocks, warp per row.
// ---------------------------------------------------------------------------
__global__ void prep_all(const float* __restrict__ X,
                         const int* __restrict__ T32, int n) {
    int tid = threadIdx.x;
    // int64-layout detection: random labels in [0,512) make 128 consecutive
    // zero odd-words impossible unless buffer is int64 (high words).
    int w = (tid < 128) ? T32[2 * tid + 1] : 0;
    int is64 = (__syncthreads_or(w) == 0) ? 1 : 0;

    int row  = (blockIdx.x * blockDim.x + tid) >> 5;
    int lane = tid & 31;
    if (row >= n) return;
    float4 v = reinterpret_cast<const float4*>(X)[(size_t)row * 32 + lane];

    // split the same float4 (lane owns cols 4*lane .. 4*lane+3)
    float xs[4] = {v.x, v.y, v.z, v.w};
    __nv_bfloat16 hb[4], hs[4];
#pragma unroll
    for (int j = 0; j < 4; j++) {
        hb[j] = __float2bfloat16(xs[j]);
        hs[j] = __float2bfloat16(xs[j] - __bfloat162float(hb[j]));
    }
    size_t o = (size_t)row * 64 + 2 * lane;
    g_Xb[o]     = __halves2bfloat162(hb[0], hb[1]);
    g_Xb[o + 1] = __halves2bfloat162(hb[2], hb[3]);
    g_Xs[o]     = __halves2bfloat162(hs[0], hs[1]);
    g_Xs[o + 1] = __halves2bfloat162(hs[2], hs[3]);

    float s = v.x * v.x + v.y * v.y + v.z * v.z + v.w * v.w;
#pragma unroll
    for (int oo = 16; oo; oo >>= 1) s += __shfl_xor_sync(0xffffffffu, s, oo);
    if (lane == 0) {
        g_sq[row]      = s;
        g_lbl[row]     = is64 ? T32[2 * row] : T32[row];
        g_ap_bits[row] = 0u;
        g_an_bits[row] = 0x7F7FFFFFu;  // FLT_MAX
    }
}

// ---------------------------------------------------------------------------
// Main: symmetric (upper-triangular) bf16x3 Gram + dual-side mining.
// Pair rowblocks (p, 63-p): exactly 130 64-col tiles -> CH chunks/pair.
// grid = 32 pairs x CH chunks; 8 warps; warp tile m32n32.
// ---------------------------------------------------------------------------
__global__ void __launch_bounds__(256, 2)
triplet_mma(int n) {
    extern __shared__ char smem[];
    const int tid  = threadIdx.x;
    const int lane = tid & 31;
    const int wid  = tid >> 5;
    const int g    = lane >> 2;     // 0..7
    const int t4   = lane & 3;      // 0..3

    const int nrb = n >> 7;            // rowblocks (64)
    const int p   = blockIdx.x / CH;   // pair id
    const int q   = blockIdx.x % CH;   // chunk id
    const int rbA = p;
    const int rbB = nrb - 1 - p;
    const int T1   = 2 * (nrb - rbA);  // tiles of rowblock A
    const int Ttot = T1 + 2 * (p + 1); // = 2*nrb + 2, constant
    const int s0 = (q * Ttot) / CH;
    const int s1 = ((q + 1) * Ttot) / CH;

    const int warp_m = wid & 3;      // 32-row band
    const int warp_n = wid >> 2;     // 32-col band

    __nv_bfloat16* Abg = reinterpret_cast<__nv_bfloat16*>(smem + SM_ABIG);
    __nv_bfloat16* Asm = reinterpret_cast<__nv_bfloat16*>(smem + SM_ASMALL);
    __nv_bfloat16* Bbg = reinterpret_cast<__nv_bfloat16*>(smem + SM_BBIG);
    __nv_bfloat16* Bsm = reinterpret_cast<__nv_bfloat16*>(smem + SM_BSMALL);
    float*         sqS = reinterpret_cast<float*>(smem + SM_SQ);
    int*           lbS = reinterpret_cast<int*>(smem + SM_LB);

    // ---- ldmatrix lane addressing (smem-fixed) ----
    const int sub = lane >> 3, rw = lane & 7;
    uint32_t aAb[2], aAs[2];
#pragma unroll
    for (int mt = 0; mt < 2; mt++) {
        int row = warp_m * 32 + mt * 16 + (sub & 1) * 8 + rw;
        int col = (sub >> 1) * 8;
        aAb[mt] = smem_u32(&Abg[row * LDA + col]);
        aAs[mt] = smem_u32(&Asm[row * LDA + col]);
    }
    uint32_t aBb[2], aBs[2];
#pragma unroll
    for (int bl = 0; bl < 2; bl++) {
        int row = warp_n * 32 + bl * 16 + (sub >> 1) * 8 + rw;
        int col = (sub & 1) * 8;
        aBb[bl] = smem_u32(&Bbg[row * LDA + col]);
        aBs[bl] = smem_u32(&Bsm[row * LDA + col]);
    }

    float sqA[4]; int lbA[4]; int rowG[4];
    float ap2[4], an2[4];
    int loaded_rb = -1;

    for (int s = s0; s < s1; s++) {
        int rb, ct;
        if (s < T1) { rb = rbA; ct = 2 * rbA + s; }
        else        { rb = rbB; ct = 2 * rbB + (s - T1); }
        const int rbase = rb << 7;
        const int cbase = ct << 6;

        __syncthreads();   // prior tile's MMAs/LDS done before smem refill

        if (rb != loaded_rb) {
            if (loaded_rb >= 0) {   // flush + reset row stats
#pragma unroll
                for (int ss = 0; ss < 4; ss++) {
                    ap2[ss] = fmaxf(ap2[ss], __shfl_xor_sync(0xffffffffu, ap2[ss], 1));
                    ap2[ss] = fmaxf(ap2[ss], __shfl_xor_sync(0xffffffffu, ap2[ss], 2));
                    an2[ss] = fminf(an2[ss], __shfl_xor_sync(0xffffffffu, an2[ss], 1));
                    an2[ss] = fminf(an2[ss], __shfl_xor_sync(0xffffffffu, an2[ss], 2));
                    if (t4 == 0) {
                        atomicMax(&g_ap_bits[rowG[ss]], __float_as_uint(fmaxf(ap2[ss], 0.0f)));
                        atomicMin(&g_an_bits[rowG[ss]], __float_as_uint(fmaxf(an2[ss], 0.0f)));
                    }
                }
            }
            {   // load A tiles for new rowblock
                const uint4* Ab = reinterpret_cast<const uint4*>(g_Xb);
                const uint4* As = reinterpret_cast<const uint4*>(g_Xs);
#pragma unroll
                for (int e = tid; e < 128 * 16; e += 256) {
                    int r = e >> 4, c8 = e & 15;
                    CP16(smem_u32(&Abg[r * LDA + c8 * 8]),
                         &Ab[(size_t)(rbase + r) * 16 + c8]);
                    CP16(smem_u32(&Asm[r * LDA + c8 * 8]),
                         &As[(size_t)(rbase + r) * 16 + c8]);
                }
            }
#pragma unroll
            for (int ss = 0; ss < 4; ss++) {
                int mt = ss >> 1, h = ss & 1;
                rowG[ss] = rbase + warp_m * 32 + mt * 16 + h * 8 + g;
                sqA[ss]  = g_sq[rowG[ss]];
                lbA[ss]  = g_lbl[rowG[ss]];
                ap2[ss]  = -1e30f;
                an2[ss]  = 3e38f;
            }
            loaded_rb = rb;
        }

        // ---- load B tile via cp.async: 64 cols x 128 bf16, big+small ----
        {
            const uint4* Bb = reinterpret_cast<const uint4*>(g_Xb);
            const uint4* Bs = reinterpret_cast<const uint4*>(g_Xs);
#pragma unroll
            for (int e = tid; e < 64 * 16; e += 256) {
                int c = e >> 4, c8 = e & 15;
                CP16(smem_u32(&Bbg[c * LDA + c8 * 8]),
                     &Bb[(size_t)(cbase + c) * 16 + c8]);
                CP16(smem_u32(&Bsm[c * LDA + c8 * 8]),
                     &Bs[(size_t)(cbase + c) * 16 + c8]);
            }
        }
        if (tid < 64) {
            CP4(smem_u32(&sqS[tid]), &g_sq[cbase + tid]);
            CP4(smem_u32(&lbS[tid]), &g_lbl[cbase + tid]);
        }
        CP_COMMIT();
        CP_WAIT0();
        __syncthreads();

        // ---- fused 3-pass mma.sync, kc-outer fragment reuse ----
        float acc[2][4][4];
#pragma unroll
        for (int mt = 0; mt < 2; mt++)
#pragma unroll
            for (int j = 0; j < 4; j++)
#pragma unroll
                for (int e = 0; e < 4; e++) acc[mt][j][e] = 0.0f;

#pragma unroll
        for (int kc = 0; kc < 8; kc++) {
            uint32_t Ab0[4], Ab1[4], As0[4], As1[4];
            uint32_t Bb0[4], Bb1[4], Bs0[4], Bs1[4];
            LDM_X4(Ab0, aAb[0] + kc * 32);
            LDM_X4(Ab1, aAb[1] + kc * 32);
            LDM_X4(As0, aAs[0] + kc * 32);
            LDM_X4(As1, aAs[1] + kc * 32);
            LDM_X4(Bb0, aBb[0] + kc * 32);
            LDM_X4(Bb1, aBb[1] + kc * 32);
            LDM_X4(Bs0, aBs[0] + kc * 32);
            LDM_X4(Bs1, aBs[1] + kc * 32);
#pragma unroll
            for (int mt = 0; mt < 2; mt++) {
                uint32_t* Ab = mt ? Ab1 : Ab0;
                uint32_t* As = mt ? As1 : As0;
#pragma unroll
                for (int j = 0; j < 4; j++) {
                    uint32_t* Bb = (j < 2) ? Bb0 : Bb1;
                    uint32_t* Bs = (j < 2) ? Bs0 : Bs1;
                    uint32_t b0b = Bb[(j & 1) * 2], b1b = Bb[(j & 1) * 2 + 1];
                    uint32_t b0s = Bs[(j & 1) * 2], b1s = Bs[(j & 1) * 2 + 1];
                    MMA16816(acc[mt][j], Ab, b0b, b1b);
                    MMA16816(acc[mt][j], As, b0b, b1b);
                    MMA16816(acc[mt][j], Ab, b0s, b1s);
                }
            }
        }

        // ---- dual-side register mining ----
        float sqC[8]; int lbC[8];
#pragma unroll
        for (int j = 0; j < 4; j++)
#pragma unroll
            for (int ec = 0; ec < 2; ec++) {
                int cl = warp_n * 32 + j * 8 + 2 * t4 + ec;
                sqC[j * 2 + ec] = sqS[cl];
                lbC[j * 2 + ec] = lbS[cl];
            }
#pragma unroll
        for (int j = 0; j < 4; j++)
#pragma unroll
            for (int ec = 0; ec < 2; ec++) {
                float cap = -1e30f, can = 3e38f;
#pragma unroll
                for (int mt = 0; mt < 2; mt++)
#pragma unroll
                    for (int h = 0; h < 2; h++) {
                        int ss = mt * 2 + h, e = h * 2 + ec;
                        float d2 = sqA[ss] + sqC[j * 2 + ec] - 2.0f * acc[mt][j][e];
                        if (lbC[j * 2 + ec] == lbA[ss]) {
                            ap2[ss] = fmaxf(ap2[ss], d2);
                            cap     = fmaxf(cap, d2);
                        } else {
                            an2[ss] = fminf(an2[ss], d2);
                            can     = fminf(can, d2);
                        }
                    }
                // col-side: reduce over g lanes (32 rows of this warp band)
                cap = fmaxf(cap, __shfl_xor_sync(0xffffffffu, cap, 4));
                cap = fmaxf(cap, __shfl_xor_sync(0xffffffffu, cap, 8));
                cap = fmaxf(cap, __shfl_xor_sync(0xffffffffu, cap, 16));
                can = fminf(can, __shfl_xor_sync(0xffffffffu, can, 4));
                can = fminf(can, __shfl_xor_sync(0xffffffffu, can, 8));
                can = fminf(can, __shfl_xor_sync(0xffffffffu, can, 16));
                if (g == 0) {
                    int c = cbase + warp_n * 32 + j * 8 + 2 * t4 + ec;
                    if (cap > -1e29f)
                        atomicMax(&g_ap_bits[c], __float_as_uint(fmaxf(cap, 0.0f)));
                    if (can < 1e38f)
                        atomicMin(&g_an_bits[c], __float_as_uint(fmaxf(can, 0.0f)));
                }
            }
    }

    // ---- final row-stat flush ----
    if (loaded_rb >= 0) {
#pragma unroll
        for (int ss = 0; ss < 4; ss++) {
            ap2[ss] = fmaxf(ap2[ss], __shfl_xor_sync(0xffffffffu, ap2[ss], 1));
            ap2[ss] = fmaxf(ap2[ss], __shfl_xor_sync(0xffffffffu, ap2[ss], 2));
            an2[ss] = fminf(an2[ss], __shfl_xor_sync(0xffffffffu, an2[ss], 1));
            an2[ss] = fminf(an2[ss], __shfl_xor_sync(0xffffffffu, an2[ss], 2));
            if (t4 == 0) {
                atomicMax(&g_ap_bits[rowG[ss]], __float_as_uint(fmaxf(ap2[ss], 0.0f)));
                atomicMin(&g_an_bits[rowG[ss]], __float_as_uint(fmaxf(an2[ss], 0.0f)));
            }
        }
    }
}

// ---------------------------------------------------------------------------
__global__ void triplet_final(float* __restrict__ out, int n, int out_size) {
    __shared__ float sL[32], sP[32];
    int tid  = threadIdx.x;
    int lane = tid & 31, w = tid >> 5;
    float ls = 0.f, ps = 0.f;
    for (int i = tid; i < n; i += 1024) {
        float ap = sqrtf(fmaxf(__uint_as_float(g_ap_bits[i]), 1e-12f));
        float an = sqrtf(fmaxf(__uint_as_float(g_an_bits[i]), 1e-12f));
        ls += fmaxf(0.0f, 0.3f - (an - ap));
        ps += (an > ap) ? 1.0f : 0.0f;
    }
#pragma unroll
    for (int o = 16; o; o >>= 1) {
        ls += __shfl_xor_sync(0xffffffffu, ls, o);
        ps += __shfl_xor_sync(0xffffffffu, ps, o);
    }
    if (lane == 0) { sL[w] = ls; sP[w] = ps; }
    __syncthreads();
    if (tid < 32) {
        ls = sL[tid]; ps = sP[tid];
#pragma unroll
        for (int o = 16; o; o >>= 1) {
            ls += __shfl_xor_sync(0xffffffffu, ls, o);
            ps += __shfl_xor_sync(0xffffffffu, ps, o);
        }
        if (tid == 0) {
            out[0] = ls / (float)n;
            if (out_size > 1) out[1] = ps / (float)n;
        }
    }
    for (int i = 2 + tid; i < out_size; i += 1024) out[i] = 0.0f;
}

// ---------------------------------------------------------------------------
extern "C" void kernel_launch(void* const* d_in, const int* in_sizes, int n_in,
                              void* d_out, int out_size) {
    const float* X   = (const float*)d_in[0];
    const int*   T32 = (const int*)d_in[1];
    int n = in_sizes[1];                 // 8192 labels (d fixed at 128)

    prep_all<<<(n * 32 + 255) / 256, 256>>>(X, T32, n);

    cudaFuncSetAttribute(triplet_mma,
                         cudaFuncAttributeMaxDynamicSharedMemorySize, SM_TOTAL);
    triplet_mma<<<(n >> 8) * CH, 256, SM_TOTAL>>>(n);   // 32 pairs x CH chunks

    triplet_final<<<1, 1024>>>((float*)d_out, n, out_size);
}

// round 13
// speedup vs baseline: 6.6270x; 1.0108x over previous
#include <cuda_runtime.h>
#include <cuda_bf16.h>
#include <cstdint>

#define NMAX 8192
#define DD   128
#define LDA  136   // bf16 elems per smem row (16B-pad: conflict-free ldmatrix)

__device__ float        g_sq[NMAX];
__device__ int          g_lbl[NMAX];
__device__ unsigned int g_ap_bits[NMAX];
__device__ unsigned int g_an_bits[NMAX];
__device__ __nv_bfloat162 g_Xb[NMAX * DD / 2];   // big terms
__device__ __nv_bfloat162 g_Xs[NMAX * DD / 2];   // small (residual) terms

// ---------------- SMEM layout (bytes) ----------------
// A resident (128 rows), B double-buffered (128 rows each), sq/lb x2.
#define TILEB     (128 * LDA * 2)                    // 34816
#define SM_ABIG   0
#define SM_ASMALL (SM_ABIG + TILEB)
#define SM_B0BIG  (SM_ASMALL + TILEB)                // 69632
#define SM_B0SML  (SM_B0BIG + TILEB)
#define SM_B1BIG  (SM_B0SML + TILEB)                 // 139264
#define SM_B1SML  (SM_B1BIG + TILEB)
#define BUFSTRIDE (SM_B1BIG - SM_B0BIG)              // 69632
#define SM_SQ     (SM_B1SML + TILEB)                 // 208896, 2x512
#define SM_LB     (SM_SQ + 1024)                     // 2x512
#define SM_TOTAL  (SM_LB + 1024)                     // ~206 KB -> 1 CTA/SM

// ---------------- PTX helpers ----------------
__device__ __forceinline__ uint32_t smem_u32(const void* p) {
    return (uint32_t)__cvta_generic_to_shared(p);
}
#define LDM_X4(r, a)                                                        \
    asm volatile("ldmatrix.sync.aligned.m8n8.x4.shared.b16 {%0,%1,%2,%3}, [%4];" \
                 : "=r"((r)[0]), "=r"((r)[1]), "=r"((r)[2]), "=r"((r)[3])   \
                 : "r"(a))
#define MMA16816(c, a, b0v, b1v)                                            \
    asm volatile("mma.sync.aligned.m16n8k16.row.col.f32.bf16.bf16.f32 "     \
                 "{%0,%1,%2,%3}, {%4,%5,%6,%7}, {%8,%9}, {%0,%1,%2,%3};"    \
                 : "+f"((c)[0]), "+f"((c)[1]), "+f"((c)[2]), "+f"((c)[3])   \
                 : "r"((a)[0]), "r"((a)[1]), "r"((a)[2]), "r"((a)[3]),      \
                   "r"(b0v), "r"(b1v))
#define CP16(dst, src)                                                      \
    asm volatile("cp.async.cg.shared.global [%0], [%1], 16;"                \
                 :: "r"(dst), "l"(src))
#define CP4(dst, src)                                                       \
    asm volatile("cp.async.ca.shared.global [%0], [%1], 4;"                 \
                 :: "r"(dst), "l"(src))
#define CP_COMMIT() asm volatile("cp.async.commit_group;")
#define CP_WAIT1()  asm volatile("cp.async.wait_group 1;" ::: "memory")

// ---------------------------------------------------------------------------
// Fused prep: label-layout detect + norms + labels + bf16 split + atomic-init.
// ---------------------------------------------------------------------------
__global__ void prep_all(const float* __restrict__ X,
                         const int* __restrict__ T32, int n) {
    int tid = threadIdx.x;
    // int64-layout detection: random labels in [0,512) cannot have 128
    // consecutive zero odd-words unless buffer is int64 (high words).
    int w = (tid < 128) ? T32[2 * tid + 1] : 0;
    int is64 = (__syncthreads_or(w) == 0) ? 1 : 0;

    int row  = (blockIdx.x * blockDim.x + tid) >> 5;
    int lane = tid & 31;
    if (row >= n) return;
    float4 v = reinterpret_cast<const float4*>(X)[(size_t)row * 32 + lane];

    float xs[4] = {v.x, v.y, v.z, v.w};
    __nv_bfloat16 hb[4], hs[4];
#pragma unroll
    for (int j = 0; j < 4; j++) {
        hb[j] = __float2bfloat16(xs[j]);
        hs[j] = __float2bfloat16(xs[j] - __bfloat162float(hb[j]));
    }
    size_t o = (size_t)row * 64 + 2 * lane;
    g_Xb[o]     = __halves2bfloat162(hb[0], hb[1]);
    g_Xb[o + 1] = __halves2bfloat162(hb[2], hb[3]);
    g_Xs[o]     = __halves2bfloat162(hs[0], hs[1]);
    g_Xs[o + 1] = __halves2bfloat162(hs[2], hs[3]);

    float s = v.x * v.x + v.y * v.y + v.z * v.z + v.w * v.w;
#pragma unroll
    for (int oo = 16; oo; oo >>= 1) s += __shfl_xor_sync(0xffffffffu, s, oo);
    if (lane == 0) {
        g_sq[row]      = s;
        g_lbl[row]     = is64 ? T32[2 * row] : T32[row];
        g_ap_bits[row] = 0u;
        g_an_bits[row] = 0x7F7FFFFFu;  // FLT_MAX
    }
}

// tile index -> (rowblock, colblock), pair-linearized upper triangle.
// pair p = (p, nrb-1-p): first (nrb-p) tiles on row p, then (p+1) on nrb-1-p.
__device__ __forceinline__ void map_tile(int s, int nrb, int& rb, int& ct) {
    int p = s / (nrb + 1);
    int r = s - p * (nrb + 1);
    if (r < nrb - p) { rb = p;           ct = p + r; }
    else             { rb = nrb - 1 - p; ct = rb + (r - (nrb - p)); }
}

// ---------------------------------------------------------------------------
// Main: symmetric bf16x3 Gram, 128x128 tiles, double-buffered cp.async
// pipeline, dual-side register mining. 512 thr = 16 warps (4x4), occ 1.
// ---------------------------------------------------------------------------
__global__ void __launch_bounds__(512, 1)
triplet_mma(int n) {
    extern __shared__ char smem[];
    const int tid  = threadIdx.x;
    const int lane = tid & 31;
    const int wid  = tid >> 5;
    const int g    = lane >> 2;     // 0..7
    const int t4   = lane & 3;      // 0..3

    const int nrb   = n >> 7;                 // 64 rowblocks
    const int total = (nrb >> 1) * (nrb + 1); // 2080 tiles
    const int s0 = (int)((long long)blockIdx.x * total / gridDim.x);
    const int s1 = (int)((long long)(blockIdx.x + 1) * total / gridDim.x);

    const int warp_m = wid & 3;      // 32-row band
    const int warp_n = wid >> 2;     // 32-col band

    __nv_bfloat16* Abg = reinterpret_cast<__nv_bfloat16*>(smem + SM_ABIG);
    __nv_bfloat16* Asm = reinterpret_cast<__nv_bfloat16*>(smem + SM_ASMALL);

    // ---- ldmatrix lane addressing (buffer-0 bases; +BUFSTRIDE for buf1) ----
    const int sub = lane >> 3, rw = lane & 7;
    uint32_t aAb[2], aAs[2];
#pragma unroll
    for (int mt = 0; mt < 2; mt++) {
        int row = warp_m * 32 + mt * 16 + (sub & 1) * 8 + rw;
        int col = (sub >> 1) * 8;
        aAb[mt] = smem_u32(&Abg[row * LDA + col]);
        aAs[mt] = smem_u32(&Asm[row * LDA + col]);
    }
    uint32_t aB0[2];   // big, buffer 0 (small = +TILEB)
#pragma unroll
    for (int bl = 0; bl < 2; bl++) {
        int row = warp_n * 32 + bl * 16 + (sub >> 1) * 8 + rw;
        int col = (sub & 1) * 8;
        aB0[bl] = smem_u32(smem + SM_B0BIG) + (row * LDA + col) * 2;
    }

    // B-tile prefetch into buffer (s&1)
    auto prefetch_B = [&](int s) {
        int rb_, ct_;
        map_tile(s, nrb, rb_, ct_);
        const int cbase = ct_ << 7;
        char* dst = smem + SM_B0BIG + (s & 1) * BUFSTRIDE;
        const uint4* Bb = reinterpret_cast<const uint4*>(g_Xb);
        const uint4* Bs = reinterpret_cast<const uint4*>(g_Xs);
#pragma unroll
        for (int e = tid; e < 128 * 16; e += 512) {
            int c = e >> 4, c8 = e & 15;
            uint32_t off = (uint32_t)(c * LDA + c8 * 8) * 2;
            CP16(smem_u32(dst) + off, &Bb[(size_t)(cbase + c) * 16 + c8]);
            CP16(smem_u32(dst) + off + TILEB, &Bs[(size_t)(cbase + c) * 16 + c8]);
        }
        if (tid < 128) {
            CP4(smem_u32(smem + SM_SQ + (s & 1) * 512) + tid * 4, &g_sq[cbase + tid]);
            CP4(smem_u32(smem + SM_LB + (s & 1) * 512) + tid * 4, &g_lbl[cbase + tid]);
        }
    };

    float sqA[4]; int lbA[4]; int rowG[4];
    float ap2[4], an2[4];
    int loaded_rb = -1;

    // preamble: start B(s0) flying
    prefetch_B(s0);
    CP_COMMIT();

    for (int s = s0; s < s1; s++) {
        int rb, ct;
        map_tile(s, nrb, rb, ct);
        const int rbase = rb << 7;
        const int cbase = ct << 7;

        __syncthreads();   // prior tile's MMAs/mining done before smem reuse

        if (rb != loaded_rb) {
            if (loaded_rb >= 0) {   // flush + reset row stats
#pragma unroll
                for (int ss = 0; ss < 4; ss++) {
                    ap2[ss] = fmaxf(ap2[ss], __shfl_xor_sync(0xffffffffu, ap2[ss], 1));
                    ap2[ss] = fmaxf(ap2[ss], __shfl_xor_sync(0xffffffffu, ap2[ss], 2));
                    an2[ss] = fminf(an2[ss], __shfl_xor_sync(0xffffffffu, an2[ss], 1));
                    an2[ss] = fminf(an2[ss], __shfl_xor_sync(0xffffffffu, an2[ss], 2));
                    if (t4 == 0) {
                        atomicMax(&g_ap_bits[rowG[ss]], __float_as_uint(fmaxf(ap2[ss], 0.0f)));
                        atomicMin(&g_an_bits[rowG[ss]], __float_as_uint(fmaxf(an2[ss], 0.0f)));
                    }
                }
            }
            {   // A load for new rowblock (own group, committed before B-prefetch)
                const uint4* Ab = reinterpret_cast<const uint4*>(g_Xb);
                const uint4* As = reinterpret_cast<const uint4*>(g_Xs);
#pragma unroll
                for (int e = tid; e < 128 * 16; e += 512) {
                    int r = e >> 4, c8 = e & 15;
                    CP16(smem_u32(&Abg[r * LDA + c8 * 8]),
                         &Ab[(size_t)(rbase + r) * 16 + c8]);
                    CP16(smem_u32(&Asm[r * LDA + c8 * 8]),
                         &As[(size_t)(rbase + r) * 16 + c8]);
                }
                CP_COMMIT();
            }
#pragma unroll
            for (int ss = 0; ss < 4; ss++) {
                int mt = ss >> 1, h = ss & 1;
                rowG[ss] = rbase + warp_m * 32 + mt * 16 + h * 8 + g;
                sqA[ss]  = g_sq[rowG[ss]];
                lbA[ss]  = g_lbl[rowG[ss]];
                ap2[ss]  = -1e30f;
                an2[ss]  = 3e38f;
            }
            loaded_rb = rb;
        }

        // prefetch next tile's B (or empty group to keep the count aligned)
        if (s + 1 < s1) prefetch_B(s + 1);
        CP_COMMIT();
        CP_WAIT1();        // B(s) (+A if reloaded) complete; B(s+1) in flight
        __syncthreads();

        const uint32_t boff = (uint32_t)((s & 1) * BUFSTRIDE);
        const float* sqS = reinterpret_cast<const float*>(smem + SM_SQ + (s & 1) * 512);
        const int*   lbS = reinterpret_cast<const int*>(smem + SM_LB + (s & 1) * 512);

        // ---- fused 3-pass mma.sync, kc-outer fragment reuse ----
        float acc[2][4][4];
#pragma unroll
        for (int mt = 0; mt < 2; mt++)
#pragma unroll
            for (int j = 0; j < 4; j++)
#pragma unroll
                for (int e = 0; e < 4; e++) acc[mt][j][e] = 0.0f;

#pragma unroll
        for (int kc = 0; kc < 8; kc++) {
            uint32_t Ab0[4], Ab1[4], As0[4], As1[4];
            uint32_t Bb0[4], Bb1[4], Bs0[4], Bs1[4];
            LDM_X4(Ab0, aAb[0] + kc * 32);
            LDM_X4(Ab1, aAb[1] + kc * 32);
            LDM_X4(As0, aAs[0] + kc * 32);
            LDM_X4(As1, aAs[1] + kc * 32);
            LDM_X4(Bb0, aB0[0] + boff + kc * 32);
            LDM_X4(Bb1, aB0[1] + boff + kc * 32);
            LDM_X4(Bs0, aB0[0] + boff + TILEB + kc * 32);
            LDM_X4(Bs1, aB0[1] + boff + TILEB + kc * 32);
#pragma unroll
            for (int mt = 0; mt < 2; mt++) {
                uint32_t* Ab = mt ? Ab1 : Ab0;
                uint32_t* As = mt ? As1 : As0;
#pragma unroll
                for (int j = 0; j < 4; j++) {
                    uint32_t* Bb = (j < 2) ? Bb0 : Bb1;
                    uint32_t* Bs = (j < 2) ? Bs0 : Bs1;
                    uint32_t b0b = Bb[(j & 1) * 2], b1b = Bb[(j & 1) * 2 + 1];
                    uint32_t b0s = Bs[(j & 1) * 2], b1s = Bs[(j & 1) * 2 + 1];
                    MMA16816(acc[mt][j], Ab, b0b, b1b);
                    MMA16816(acc[mt][j], As, b0b, b1b);
                    MMA16816(acc[mt][j], Ab, b0s, b1s);
                }
            }
        }

        // ---- dual-side register mining ----
        float sqC[8]; int lbC[8];
#pragma unroll
        for (int j = 0; j < 4; j++)
#pragma unroll
            for (int ec = 0; ec < 2; ec++) {
                int cl = warp_n * 32 + j * 8 + 2 * t4 + ec;
                sqC[j * 2 + ec] = sqS[cl];
                lbC[j * 2 + ec] = lbS[cl];
            }
#pragma unroll
        for (int j = 0; j < 4; j++)
#pragma unroll
            for (int ec = 0; ec < 2; ec++) {
                float cap = -1e30f, can = 3e38f;
#pragma unroll
                for (int mt = 0; mt < 2; mt++)
#pragma unroll
                    for (int h = 0; h < 2; h++) {
                        int ss = mt * 2 + h, e = h * 2 + ec;
                        float d2 = sqA[ss] + sqC[j * 2 + ec] - 2.0f * acc[mt][j][e];
                        if (lbC[j * 2 + ec] == lbA[ss]) {
                            ap2[ss] = fmaxf(ap2[ss], d2);
                            cap     = fmaxf(cap, d2);
                        } else {
                            an2[ss] = fminf(an2[ss], d2);
                            can     = fminf(can, d2);
                        }
                    }
                cap = fmaxf(cap, __shfl_xor_sync(0xffffffffu, cap, 4));
                cap = fmaxf(cap, __shfl_xor_sync(0xffffffffu, cap, 8));
                cap = fmaxf(cap, __shfl_xor_sync(0xffffffffu, cap, 16));
                can = fminf(can, __shfl_xor_sync(0xffffffffu, can, 4));
                can = fminf(can, __shfl_xor_sync(0xffffffffu, can, 8));
                can = fminf(can, __shfl_xor_sync(0xffffffffu, can, 16));
                if (g == 0) {
                    int c = cbase + warp_n * 32 + j * 8 + 2 * t4 + ec;
                    if (cap > -1e29f)
                        atomicMax(&g_ap_bits[c], __float_as_uint(fmaxf(cap, 0.0f)));
                    if (can < 1e38f)
                        atomicMin(&g_an_bits[c], __float_as_uint(fmaxf(can, 0.0f)));
                }
            }
    }

    // ---- final row-stat flush ----
    if (loaded_rb >= 0) {
#pragma unroll
        for (int ss = 0; ss < 4; ss++) {
            ap2[ss] = fmaxf(ap2[ss], __shfl_xor_sync(0xffffffffu, ap2[ss], 1));
            ap2[ss] = fmaxf(ap2[ss], __shfl_xor_sync(0xffffffffu, ap2[ss], 2));
            an2[ss] = fminf(an2[ss], __shfl_xor_sync(0xffffffffu, an2[ss], 1));
            an2[ss] = fminf(an2[ss], __shfl_xor_sync(0xffffffffu, an2[ss], 2));
            if (t4 == 0) {
                atomicMax(&g_ap_bits[rowG[ss]], __float_as_uint(fmaxf(ap2[ss], 0.0f)));
                atomicMin(&g_an_bits[rowG[ss]], __float_as_uint(fmaxf(an2[ss], 0.0f)));
            }
        }
    }
}

// ---------------------------------------------------------------------------
__global__ void triplet_final(float* __restrict__ out, int n, int out_size) {
    __shared__ float sL[32], sP[32];
    int tid  = threadIdx.x;
    int lane = tid & 31, w = tid >> 5;
    float ls = 0.f, ps = 0.f;
    for (int i = tid; i < n; i += 1024) {
        float ap = sqrtf(fmaxf(__uint_as_float(g_ap_bits[i]), 1e-12f));
        float an = sqrtf(fmaxf(__uint_as_float(g_an_bits[i]), 1e-12f));
        ls += fmaxf(0.0f, 0.3f - (an - ap));
        ps += (an > ap) ? 1.0f : 0.0f;
    }
#pragma unroll
    for (int o = 16; o; o >>= 1) {
        ls += __shfl_xor_sync(0xffffffffu, ls, o);
        ps += __shfl_xor_sync(0xffffffffu, ps, o);
    }
    if (lane == 0) { sL[w] = ls; sP[w] = ps; }
    __syncthreads();
    if (tid < 32) {
        ls = sL[tid]; ps = sP[tid];
#pragma unroll
        for (int o = 16; o; o >>= 1) {
            ls += __shfl_xor_sync(0xffffffffu, ls, o);
            ps += __shfl_xor_sync(0xffffffffu, ps, o);
        }
        if (tid == 0) {
            out[0] = ls / (float)n;
            if (out_size > 1) out[1] = ps / (float)n;
        }
    }
    for (int i = 2 + tid; i < out_size; i += 1024) out[i] = 0.0f;
}

// ---------------------------------------------------------------------------
extern "C" void kernel_launch(void* const* d_in, const int* in_sizes, int n_in,
                              void* d_out, int out_size) {
    const float* X   = (const float*)d_in[0];
    const int*   T32 = (const int*)d_in[1];
    int n = in_sizes[1];                 // 8192 labels (d fixed at 128)

    prep_all<<<(n * 32 + 255) / 256, 256>>>(X, T32, n);

    int sms = 148;
    cudaDeviceGetAttribute(&sms, cudaDevAttrMultiProcessorCount, 0);
    int nrb = n >> 7;
    int total = (nrb >> 1) * (nrb + 1);
    int grid = (sms < total) ? sms : total;

    cudaFuncSetAttribute(triplet_mma,
                         cudaFuncAttributeMaxDynamicSharedMemorySize, SM_TOTAL);
    triplet_mma<<<grid, 512, SM_TOTAL>>>(n);

    triplet_final<<<1, 1024>>>((float*)d_out, n, out_size);
}

// round 15
// speedup vs baseline: 6.6928x; 1.0099x over previous
#include <cuda_runtime.h>
#include <cuda_bf16.h>
#include <cstdint>

#define NMAX 8192
#define DD   128
#define LDA  136   // bf16 elems per smem row (16B-pad: conflict-free ldmatrix)

__device__ float        g_sq[NMAX];
__device__ int          g_lbl[NMAX];
__device__ unsigned int g_ap_bits[NMAX];
__device__ unsigned int g_an_bits[NMAX];
__device__ __nv_bfloat162 g_Xb[NMAX * DD / 2];   // big terms
__device__ __nv_bfloat162 g_Xs[NMAX * DD / 2];   // small (residual) terms

// ---------------- SMEM layout (bytes) ----------------
// A resident (128 rows), B single-buffered (256 rows), sq/lb double-buffered.
#define SM_ABIG   0
#define SM_ASMALL (SM_ABIG + 128 * LDA * 2)          // 34816
#define SM_BBIG   (SM_ASMALL + 128 * LDA * 2)        // 69632
#define SM_BSMALL (SM_BBIG + 256 * LDA * 2)          // 139264
#define BS_OFF    (SM_BSMALL - SM_BBIG)              // 69632
#define SM_SQ     (SM_BSMALL + 256 * LDA * 2)        // 208896, 2 x 1024
#define SM_LB     (SM_SQ + 2048)                     // 2 x 1024
#define SM_TOTAL  (SM_LB + 2048)                     // 212992 B (~208 KB)

// ---------------- PTX helpers ----------------
__device__ __forceinline__ uint32_t smem_u32(const void* p) {
    return (uint32_t)__cvta_generic_to_shared(p);
}
#define LDM_X4(r, a)                                                        \
    asm volatile("ldmatrix.sync.aligned.m8n8.x4.shared.b16 {%0,%1,%2,%3}, [%4];" \
                 : "=r"((r)[0]), "=r"((r)[1]), "=r"((r)[2]), "=r"((r)[3])   \
                 : "r"(a))
#define MMA16816(c, a, b0v, b1v)                                            \
    asm volatile("mma.sync.aligned.m16n8k16.row.col.f32.bf16.bf16.f32 "     \
                 "{%0,%1,%2,%3}, {%4,%5,%6,%7}, {%8,%9}, {%0,%1,%2,%3};"    \
                 : "+f"((c)[0]), "+f"((c)[1]), "+f"((c)[2]), "+f"((c)[3])   \
                 : "r"((a)[0]), "r"((a)[1]), "r"((a)[2]), "r"((a)[3]),      \
                   "r"(b0v), "r"(b1v))
#define CP16(dst, src)                                                      \
    asm volatile("cp.async.cg.shared.global [%0], [%1], 16;"                \
                 :: "r"(dst), "l"(src))
#define CP4(dst, src)                                                       \
    asm volatile("cp.async.ca.shared.global [%0], [%1], 4;"                 \
                 :: "r"(dst), "l"(src))
#define CP_COMMIT() asm volatile("cp.async.commit_group;")
#define CP_WAIT0()  asm volatile("cp.async.wait_group 0;" ::: "memory")

// ---------------------------------------------------------------------------
// Fused prep: label-layout detect + norms + labels + bf16 split + atomic-init.
// ---------------------------------------------------------------------------
__global__ void prep_all(const float* __restrict__ X,
                         const int* __restrict__ T32, int n) {
    int tid = threadIdx.x;
    // int64-layout detection: random labels in [0,512) cannot have 128
    // consecutive zero odd-words unless buffer is int64 (high words).
    int w = (tid < 128) ? T32[2 * tid + 1] : 0;
    int is64 = (__syncthreads_or(w) == 0) ? 1 : 0;

    int row  = (blockIdx.x * blockDim.x + tid) >> 5;
    int lane = tid & 31;
    if (row >= n) return;
    float4 v = reinterpret_cast<const float4*>(X)[(size_t)row * 32 + lane];

    float xs[4] = {v.x, v.y, v.z, v.w};
    __nv_bfloat16 hb[4], hs[4];
#pragma unroll
    for (int j = 0; j < 4; j++) {
        hb[j] = __float2bfloat16(xs[j]);
        hs[j] = __float2bfloat16(xs[j] - __bfloat162float(hb[j]));
    }
    size_t o = (size_t)row * 64 + 2 * lane;
    g_Xb[o]     = __halves2bfloat162(hb[0], hb[1]);
    g_Xb[o + 1] = __halves2bfloat162(hb[2], hb[3]);
    g_Xs[o]     = __halves2bfloat162(hs[0], hs[1]);
    g_Xs[o + 1] = __halves2bfloat162(hs[2], hs[3]);

    float s = v.x * v.x + v.y * v.y + v.z * v.z + v.w * v.w;
#pragma unroll
    for (int oo = 16; oo; oo >>= 1) s += __shfl_xor_sync(0xffffffffu, s, oo);
    if (lane == 0) {
        g_sq[row]      = s;
        g_lbl[row]     = is64 ? T32[2 * row] : T32[row];
        g_ap_bits[row] = 0u;
        g_an_bits[row] = 0x7F7FFFFFu;  // FLT_MAX
    }
}

// tile s -> (rowblock of 128, col tile of 256). Pair (p, nrb-1-p) has
// (nct+1) tiles (constant). Odd rowblocks overlap 128 cols below diagonal
// (redundant but correct: min/max idempotent).
__device__ __forceinline__ void map_tile(int s, int nrb, int nct,
                                         int& rb, int& ct) {
    int tpp = nct + 1;
    int p = s / tpp;
    int r = s - p * tpp;
    int T1 = nct - (p >> 1);
    if (r < T1) { rb = p;           ct = (p >> 1) + r; }
    else        { rb = nrb - 1 - p; ct = (rb >> 1) + (r - T1); }
}

// ---------------------------------------------------------------------------
// Main: symmetric bf16x3 Gram, 128x256 CTA tiles, warp tile m32n64,
// dual-side register mining, B-load overlapped with mining.
// 512 thr = 16 warps (4m x 4n), occ 1.
// ---------------------------------------------------------------------------
__global__ void __launch_bounds__(512, 1)
triplet_mma(int n) {
    extern __shared__ char smem[];
    const int tid  = threadIdx.x;
    const int lane = tid & 31;
    const int wid  = tid >> 5;
    const int g    = lane >> 2;     // 0..7
    const int t4   = lane & 3;      // 0..3

    const int nrb   = n >> 7;               // 64 rowblocks (128 rows)
    const int nct   = n >> 8;               // 32 col tiles (256 cols)
    const int total = (nrb >> 1) * (nct + 1);  // 1056 tiles
    const int s0 = (int)((long long)blockIdx.x * total / gridDim.x);
    const int s1 = (int)((long long)(blockIdx.x + 1) * total / gridDim.x);
    if (s0 >= s1) return;

    const int warp_m = wid & 3;      // 32-row band
    const int warp_n = wid >> 2;     // 64-col band

    __nv_bfloat16* Abg = reinterpret_cast<__nv_bfloat16*>(smem + SM_ABIG);
    __nv_bfloat16* Asm = reinterpret_cast<__nv_bfloat16*>(smem + SM_ASMALL);

    // ---- ldmatrix lane addressing ----
    const int sub = lane >> 3, rw = lane & 7;
    uint32_t aAb[2], aAs[2];
#pragma unroll
    for (int mt = 0; mt < 2; mt++) {
        int row = warp_m * 32 + mt * 16 + (sub & 1) * 8 + rw;
        int col = (sub >> 1) * 8;
        aAb[mt] = smem_u32(&Abg[row * LDA + col]);
        aAs[mt] = smem_u32(&Asm[row * LDA + col]);
    }
    uint32_t aB[4];   // big bases for the 4 n16 sub-tiles (small = +BS_OFF)
#pragma unroll
    for (int bl = 0; bl < 4; bl++) {
        int row = warp_n * 64 + bl * 16 + (sub >> 1) * 8 + rw;
        int col = (sub & 1) * 8;
        aB[bl] = smem_u32(smem + SM_BBIG) + (uint32_t)(row * LDA + col) * 2;
    }

    auto load_A = [&](int rbase) {
        const uint4* Ab = reinterpret_cast<const uint4*>(g_Xb);
        const uint4* As = reinterpret_cast<const uint4*>(g_Xs);
#pragma unroll
        for (int e = tid; e < 128 * 16; e += 512) {
            int r = e >> 4, c8 = e & 15;
            CP16(smem_u32(&Abg[r * LDA + c8 * 8]),
                 &Ab[(size_t)(rbase + r) * 16 + c8]);
            CP16(smem_u32(&Asm[r * LDA + c8 * 8]),
                 &As[(size_t)(rbase + r) * 16 + c8]);
        }
    };
    auto load_B = [&](int s, int cbase) {
        const uint4* Bb = reinterpret_cast<const uint4*>(g_Xb);
        const uint4* Bs = reinterpret_cast<const uint4*>(g_Xs);
#pragma unroll
        for (int e = tid; e < 256 * 16; e += 512) {
            int c = e >> 4, c8 = e & 15;
            uint32_t off = (uint32_t)(c * LDA + c8 * 8) * 2;
            CP16(smem_u32(smem + SM_BBIG) + off,
                 &Bb[(size_t)(cbase + c) * 16 + c8]);
            CP16(smem_u32(smem + SM_BBIG) + off + BS_OFF,
                 &Bs[(size_t)(cbase + c) * 16 + c8]);
        }
        if (tid < 256) {
            CP4(smem_u32(smem + SM_SQ + (s & 1) * 1024) + tid * 4, &g_sq[cbase + tid]);
            CP4(smem_u32(smem + SM_LB + (s & 1) * 1024) + tid * 4, &g_lbl[cbase + tid]);
        }
    };

    float sqA[4]; int lbA[4];
    float ap2[4], an2[4];

    auto init_rows = [&](int rbase) {
#pragma unroll
        for (int ss = 0; ss < 4; ss++) {
            int mt = ss >> 1, h = ss & 1;
            int rG = rbase + warp_m * 32 + mt * 16 + h * 8 + g;
            sqA[ss] = g_sq[rG];
            lbA[ss] = g_lbl[rG];
            ap2[ss] = -1e30f;
            an2[ss] = 3e38f;
        }
    };
    auto flush_rows = [&](int rbase) {
#pragma unroll
        for (int ss = 0; ss < 4; ss++) {
            float a = ap2[ss], b = an2[ss];
            a = fmaxf(a, __shfl_xor_sync(0xffffffffu, a, 1));
            a = fmaxf(a, __shfl_xor_sync(0xffffffffu, a, 2));
            b = fminf(b, __shfl_xor_sync(0xffffffffu, b, 1));
            b = fminf(b, __shfl_xor_sync(0xffffffffu, b, 2));
            if (t4 == 0) {
                int mt = ss >> 1, h = ss & 1;
                int rG = rbase + warp_m * 32 + mt * 16 + h * 8 + g;
                atomicMax(&g_ap_bits[rG], __float_as_uint(fmaxf(a, 0.0f)));
                atomicMin(&g_an_bits[rG], __float_as_uint(fmaxf(b, 0.0f)));
            }
        }
    };

    // ---- preamble ----
    int rb, ct;
    map_tile(s0, nrb, nct, rb, ct);
    load_A(rb << 7);
    load_B(s0, ct << 8);
    CP_COMMIT();
    init_rows(rb << 7);

    for (int s = s0; s < s1; s++) {
        const int cbase = ct << 8;
        CP_WAIT0();
        __syncthreads();      // B(s)/sq/lb(s)/(A) resident; prior prefetch safe

        // ---- fused 3-pass mma.sync ----
        float acc[2][8][4];
#pragma unroll
        for (int mt = 0; mt < 2; mt++)
#pragma unroll
            for (int j = 0; j < 8; j++)
#pragma unroll
                for (int e = 0; e < 4; e++) acc[mt][j][e] = 0.0f;

#pragma unroll
        for (int kc = 0; kc < 8; kc++) {
            uint32_t Ab0[4], Ab1[4], As0[4], As1[4];
            LDM_X4(Ab0, aAb[0] + kc * 32);
            LDM_X4(Ab1, aAb[1] + kc * 32);
            LDM_X4(As0, aAs[0] + kc * 32);
            LDM_X4(As1, aAs[1] + kc * 32);
#pragma unroll
            for (int nh = 0; nh < 2; nh++) {
                uint32_t Bb0[4], Bb1[4], Bs0[4], Bs1[4];
                LDM_X4(Bb0, aB[2 * nh]     + kc * 32);
                LDM_X4(Bb1, aB[2 * nh + 1] + kc * 32);
                LDM_X4(Bs0, aB[2 * nh]     + BS_OFF + kc * 32);
                LDM_X4(Bs1, aB[2 * nh + 1] + BS_OFF + kc * 32);
#pragma unroll
                for (int mt = 0; mt < 2; mt++) {
                    uint32_t* Ab = mt ? Ab1 : Ab0;
                    uint32_t* As = mt ? As1 : As0;
#pragma unroll
                    for (int jl = 0; jl < 4; jl++) {
                        int j = nh * 4 + jl;
                        uint32_t* Bb = (jl < 2) ? Bb0 : Bb1;
                        uint32_t* Bs = (jl < 2) ? Bs0 : Bs1;
                        uint32_t b0b = Bb[(jl & 1) * 2], b1b = Bb[(jl & 1) * 2 + 1];
                        uint32_t b0s = Bs[(jl & 1) * 2], b1s = Bs[(jl & 1) * 2 + 1];
                        MMA16816(acc[mt][j], Ab, b0b, b1b);
                        MMA16816(acc[mt][j], As, b0b, b1b);
                        MMA16816(acc[mt][j], Ab, b0s, b1s);
                    }
                }
            }
        }

        __syncthreads();      // all LDSM reads of A/B done

        // ---- prefetch next tile (overlaps mining below) ----
        int rbn = rb, ctn = ct;
        bool newA = false;
        if (s + 1 < s1) {
            map_tile(s + 1, nrb, nct, rbn, ctn);
            if (rbn != rb) { load_A(rbn << 7); newA = true; }
            load_B(s + 1, ctn << 8);
            CP_COMMIT();
        }

        // ---- dual-side register mining (reads sq/lb buf s&1, acc) ----
        const float* sqS = reinterpret_cast<const float*>(smem + SM_SQ + (s & 1) * 1024);
        const int*   lbS = reinterpret_cast<const int*>(smem + SM_LB + (s & 1) * 1024);
#pragma unroll
        for (int j = 0; j < 8; j++)
#pragma unroll
            for (int ec = 0; ec < 2; ec++) {
                int cl = warp_n * 64 + j * 8 + 2 * t4 + ec;
                float sq_c = sqS[cl];
                int   lb_c = lbS[cl];
                float cap = -1e30f, can = 3e38f;
#pragma unroll
                for (int mt = 0; mt < 2; mt++)
#pragma unroll
                    for (int h = 0; h < 2; h++) {
                        int ss = mt * 2 + h, e = h * 2 + ec;
                        float d2 = sqA[ss] + sq_c - 2.0f * acc[mt][j][e];
                        if (lb_c == lbA[ss]) {
                            ap2[ss] = fmaxf(ap2[ss], d2);
                            cap     = fmaxf(cap, d2);
                        } else {
                            an2[ss] = fminf(an2[ss], d2);
                            can     = fminf(can, d2);
                        }
                    }
                cap = fmaxf(cap, __shfl_xor_sync(0xffffffffu, cap, 4));
                cap = fmaxf(cap, __shfl_xor_sync(0xffffffffu, cap, 8));
                cap = fmaxf(cap, __shfl_xor_sync(0xffffffffu, cap, 16));
                can = fminf(can, __shfl_xor_sync(0xffffffffu, can, 4));
                can = fminf(can, __shfl_xor_sync(0xffffffffu, can, 8));
                can = fminf(can, __shfl_xor_sync(0xffffffffu, can, 16));
                if (g == 0) {
                    int c = cbase + cl;
                    if (cap > -1e29f)
                        atomicMax(&g_ap_bits[c], __float_as_uint(fmaxf(cap, 0.0f)));
                    if (can < 1e38f)
                        atomicMin(&g_an_bits[c], __float_as_uint(fmaxf(can, 0.0f)));
                }
            }

        // ---- rowblock switch: flush old stats, init new ----
        if (newA) {
            flush_rows(rb << 7);
            init_rows(rbn << 7);
        }
        rb = rbn; ct = ctn;
    }

    flush_rows(rb << 7);
}

// ---------------------------------------------------------------------------
__global__ void triplet_final(float* __restrict__ out, int n, int out_size) {
    __shared__ float sL[32], sP[32];
    int tid  = threadIdx.x;
    int lane = tid & 31, w = tid >> 5;
    float ls = 0.f, ps = 0.f;
    for (int i = tid; i < n; i += 1024) {
        float ap = sqrtf(fmaxf(__uint_as_float(g_ap_bits[i]), 1e-12f));
        float an = sqrtf(fmaxf(__uint_as_float(g_an_bits[i]), 1e-12f));
        ls += fmaxf(0.0f, 0.3f - (an - ap));
        ps += (an > ap) ? 1.0f : 0.0f;
    }
#pragma unroll
    for (int o = 16; o; o >>= 1) {
        ls += __shfl_xor_sync(0xffffffffu, ls, o);
        ps += __shfl_xor_sync(0xffffffffu, ps, o);
    }
    if (lane == 0) { sL[w] = ls; sP[w] = ps; }
    __syncthreads();
    if (tid < 32) {
        ls = sL[tid]; ps = sP[tid];
#pragma unroll
        for (int o = 16; o; o >>= 1) {
            ls += __shfl_xor_sync(0xffffffffu, ls, o);
            ps += __shfl_xor_sync(0xffffffffu, ps, o);
        }
        if (tid == 0) {
            out[0] = ls / (float)n;
            if (out_size > 1) out[1] = ps / (float)n;
        }
    }
    for (int i = 2 + tid; i < out_size; i += 1024) out[i] = 0.0f;
}

// ---------------------------------------------------------------------------
extern "C" void kernel_launch(void* const* d_in, const int* in_sizes, int n_in,
                              void* d_out, int out_size) {
    const float* X   = (const float*)d_in[0];
    const int*   T32 = (const int*)d_in[1];
    int n = in_sizes[1];                 // 8192 labels (d fixed at 128)

    prep_all<<<(n * 32 + 255) / 256, 256>>>(X, T32, n);

    int sms = 148;
    cudaDeviceGetAttribute(&sms, cudaDevAttrMultiProcessorCount, 0);
    int nrb = n >> 7, nct = n >> 8;
    int total = (nrb >> 1) * (nct + 1);
    int grid = (sms < total) ? sms : total;

    cudaFuncSetAttribute(triplet_mma,
                         cudaFuncAttributeMaxDynamicSharedMemorySize, SM_TOTAL);
    triplet_mma<<<grid, 512, SM_TOTAL>>>(n);

    triplet_final<<<1, 1024>>>((float*)d_out, n, out_size);
}